// round 1
// baseline (speedup 1.0000x reference)
#include <cuda_runtime.h>
#include <math.h>

#define NN 50000
#define EE 800000

// ---------------- scratch (device globals; no allocation) ----------------
__device__ float g_ae1[EE*4];
__device__ float g_ae2[EE*4];
__device__ float g_araw[EE*4];
__device__ float g_h0[NN*128];
__device__ float g_h1[NN*128];
__device__ float g_h2[NN*128];
__device__ float g_xs[NN*128];
__device__ float g_agg[NN*128];
__device__ float g_asrc[NN*4];
__device__ float g_adst[NN*4];
__device__ float g_amax[NN*4];
__device__ float g_den[NN*4];
__device__ float g_M[32];   // [conv*16 + j*4 + h]

// ---------------- helpers ----------------
__device__ __forceinline__ void atomicMaxF(float* a, float v){
    if (v >= 0.f) atomicMax((int*)a, __float_as_int(v));
    else          atomicMin((unsigned int*)a, __float_as_uint(v));
}

__device__ __forceinline__ void redAdd4(float* p, float a, float b, float c, float d){
    asm volatile("red.global.add.v4.f32 [%0], {%1,%2,%3,%4};"
                 :: "l"(p), "f"(a), "f"(b), "f"(c), "f"(d) : "memory");
}

// ---------------- precompute 4x4 edge-attention matrices ----------------
__global__ void k_prep(const float* le1, const float* ae1,
                       const float* le2, const float* ae2){
    int t = threadIdx.x;
    if (t >= 32) return;
    int which = t >> 4, j = (t >> 2) & 3, h = t & 3;
    const float* le = which ? le2 : le1;   // [128,4] row-major
    const float* ae = which ? ae2 : ae1;   // [4,32]  row-major
    float s = 0.f;
    for (int c = 0; c < 32; c++)
        s += le[(h*32+c)*4 + j] * ae[h*32+c];
    g_M[which*16 + j*4 + h] = s;
}

// ---------------- edge encoder fused with a_edge = e @ M ----------------
__global__ void k_edge(const float* __restrict__ ea,
                       const float* __restrict__ w1, const float* __restrict__ b1,
                       const float* __restrict__ w2, const float* __restrict__ b2){
    __shared__ float sw1[256], sb1[32], sw2[128], sb2[4], sM[32];
    int tid = threadIdx.x;
    if (tid < 256) sw1[tid] = w1[tid];
    if (tid < 32)  sb1[tid] = b1[tid];
    if (tid < 128) sw2[tid] = w2[tid];
    if (tid < 4)   sb2[tid] = b2[tid];
    if (tid >= 32 && tid < 64) sM[tid-32] = g_M[tid-32];
    __syncthreads();
    int e = blockIdx.x*256 + tid;
    if (e >= EE) return;
    float4 v0 = ((const float4*)ea)[e*2];
    float4 v1 = ((const float4*)ea)[e*2+1];
    float av[8] = {v0.x,v0.y,v0.z,v0.w,v1.x,v1.y,v1.z,v1.w};
    float e0=sb2[0], e1=sb2[1], e2=sb2[2], e3=sb2[3];
    #pragma unroll
    for (int c=0;c<32;c++){
        float hv = sb1[c];
        #pragma unroll
        for (int j=0;j<8;j++) hv = fmaf(sw1[c*8+j], av[j], hv);
        hv = fmaxf(hv, 0.f);
        e0 = fmaf(sw2[c],    hv, e0);
        e1 = fmaf(sw2[32+c], hv, e1);
        e2 = fmaf(sw2[64+c], hv, e2);
        e3 = fmaf(sw2[96+c], hv, e3);
    }
    float4 r1, r2;
    r1.x = e0*sM[0] + e1*sM[4] + e2*sM[8]  + e3*sM[12];
    r1.y = e0*sM[1] + e1*sM[5] + e2*sM[9]  + e3*sM[13];
    r1.z = e0*sM[2] + e1*sM[6] + e2*sM[10] + e3*sM[14];
    r1.w = e0*sM[3] + e1*sM[7] + e2*sM[11] + e3*sM[15];
    r2.x = e0*sM[16]+ e1*sM[20]+ e2*sM[24] + e3*sM[28];
    r2.y = e0*sM[17]+ e1*sM[21]+ e2*sM[25] + e3*sM[29];
    r2.z = e0*sM[18]+ e1*sM[22]+ e2*sM[26] + e3*sM[30];
    r2.w = e0*sM[19]+ e1*sM[23]+ e2*sM[27] + e3*sM[31];
    ((float4*)g_ae1)[e] = r1;
    ((float4*)g_ae2)[e] = r2;
}

// ---------------- conv1 node transforms: h0, xs1, a_src1, a_dst1 ----------------
__global__ void k_node1(const float* __restrict__ x,
                        const float* __restrict__ pw, const float* __restrict__ pb,
                        const float* __restrict__ lw,
                        const float* __restrict__ asv, const float* __restrict__ adv){
    __shared__ float sWp[16*129], sWl[16*129];
    __shared__ float sx[16*17];
    int tid = threadIdx.x;
    float attS = asv[tid], attD = adv[tid], pbd = pb[tid];
    for (int i=tid;i<2048;i+=128){
        int d=i>>4, k=i&15;
        sWp[k*129+d] = pw[i];
        sWl[k*129+d] = lw[i];
    }
    int n0 = blockIdx.x*16;
    for (int i=tid;i<256;i+=128){
        int n=i>>4, k=i&15;
        int node=n0+n;
        sx[n*17+k] = (node<NN) ? x[node*16+k] : 0.f;
    }
    __syncthreads();
    float acc0[16], acc1[16];
    #pragma unroll
    for (int n=0;n<16;n++){ acc0[n]=pbd; acc1[n]=0.f; }
    #pragma unroll
    for (int k=0;k<16;k++){
        float wp=sWp[k*129+tid], wl=sWl[k*129+tid];
        #pragma unroll
        for (int n=0;n<16;n++){
            float xv = sx[n*17+k];
            acc0[n] = fmaf(xv, wp, acc0[n]);
            acc1[n] = fmaf(xv, wl, acc1[n]);
        }
    }
    int lane = tid&31, h = tid>>5;
    for (int n=0;n<16;n++){
        int node=n0+n;
        if (node>=NN) break;
        g_h0[node*128+tid] = acc0[n];
        g_xs[node*128+tid] = acc1[n];
        float s = acc1[n]*attS, dd = acc1[n]*attD;
        #pragma unroll
        for (int o=16;o>0;o>>=1){
            s  += __shfl_down_sync(0xffffffffu, s, o);
            dd += __shfl_down_sync(0xffffffffu, dd, o);
        }
        if (lane==0){ g_asrc[node*4+h]=s; g_adst[node*4+h]=dd; }
    }
}

// ---------------- init per-conv accumulators ----------------
__global__ void k_fill(){
    int i = blockIdx.x*blockDim.x + threadIdx.x;
    int stride = gridDim.x*blockDim.x;
    for (int j=i;j<NN*4;j+=stride){ g_amax[j] = -1e30f; g_den[j] = 0.f; }
    for (int j=i;j<NN*128;j+=stride) g_agg[j] = 0.f;
}

// ---------------- alpha pass 1: leaky_relu + segment max ----------------
__global__ void k_amax(const int* __restrict__ ei, int conv){
    int e = blockIdx.x*256 + threadIdx.x;
    if (e >= EE) return;
    int s = ei[e], d = ei[EE+e];
    const float4* ae = (const float4*)(conv ? g_ae2 : g_ae1);
    float4 as = ((const float4*)g_asrc)[s];
    float4 ad = ((const float4*)g_adst)[d];
    float4 av = ae[e];
    float4 r;
    r.x = as.x+ad.x+av.x; r.x = r.x>0.f ? r.x : 0.2f*r.x;
    r.y = as.y+ad.y+av.y; r.y = r.y>0.f ? r.y : 0.2f*r.y;
    r.z = as.z+ad.z+av.z; r.z = r.z>0.f ? r.z : 0.2f*r.z;
    r.w = as.w+ad.w+av.w; r.w = r.w>0.f ? r.w : 0.2f*r.w;
    ((float4*)g_araw)[e] = r;
    atomicMaxF(&g_amax[d*4+0], r.x);
    atomicMaxF(&g_amax[d*4+1], r.y);
    atomicMaxF(&g_amax[d*4+2], r.z);
    atomicMaxF(&g_amax[d*4+3], r.w);
}

// ---------------- alpha pass 2: exp + segment sum ----------------
__global__ void k_asum(const int* __restrict__ ei){
    int e = blockIdx.x*256 + threadIdx.x;
    if (e >= EE) return;
    int d = ei[EE+e];
    float4 a = ((const float4*)g_araw)[e];
    float4 m = ((const float4*)g_amax)[d];
    float4 ex = make_float4(__expf(a.x-m.x), __expf(a.y-m.y),
                            __expf(a.z-m.z), __expf(a.w-m.w));
    ((float4*)g_araw)[e] = ex;
    redAdd4(&g_den[d*4], ex.x, ex.y, ex.z, ex.w);
}

// ---------------- message scatter: warp per edge, vectorized red ----------------
__global__ void k_msg(const int* __restrict__ ei){
    int gt = blockIdx.x*256 + threadIdx.x;
    int e = gt >> 5, lane = gt & 31;
    if (e >= EE) return;
    int s = ei[e], d = ei[EE+e];
    int h = lane >> 3;
    float alpha = g_araw[e*4+h] / (g_den[d*4+h] + 1e-16f);
    float4 xv = ((const float4*)g_xs)[s*32 + lane];
    redAdd4(&g_agg[d*128 + lane*4], xv.x*alpha, xv.y*alpha, xv.z*alpha, xv.w*alpha);
}

// ---------------- epilogue: bias + ELU + residual + LayerNorm ----------------
__global__ void k_epi(const float* __restrict__ bias, const float* __restrict__ gam,
                      const float* __restrict__ bet, int conv){
    __shared__ float red[8];
    int node = blockIdx.x, d = threadIdx.x;
    const float* hp = conv ? g_h1 : g_h0;
    float*       ho = conv ? g_h2 : g_h1;
    float v = g_agg[node*128+d] + bias[d];
    v = (v > 0.f) ? v : (expf(v) - 1.f);
    v += hp[node*128+d];
    float s = v, s2 = v*v;
    #pragma unroll
    for (int o=16;o>0;o>>=1){
        s  += __shfl_down_sync(0xffffffffu, s,  o);
        s2 += __shfl_down_sync(0xffffffffu, s2, o);
    }
    int lane = d&31, w = d>>5;
    if (lane==0){ red[w]=s; red[4+w]=s2; }
    __syncthreads();
    if (d==0){
        float ts  = red[0]+red[1]+red[2]+red[3];
        float ts2 = red[4]+red[5]+red[6]+red[7];
        red[0] = ts  * (1.f/128.f);
        red[1] = ts2 * (1.f/128.f);
    }
    __syncthreads();
    float mu = red[0], var = red[1]-mu*mu;
    float r = rsqrtf(var + 1e-5f);
    ho[node*128+d] = (v-mu)*r*gam[d] + bet[d];
}

// ---------------- conv2 node transform: xs2 = h1 @ c2_lin^T + attn dots ----------------
__global__ void k_node2(const float* __restrict__ lin,
                        const float* __restrict__ asv, const float* __restrict__ adv){
    __shared__ float sW[32*129];
    __shared__ __align__(16) float sIn[32*36];
    int tid = threadIdx.x;
    float attS = asv[tid], attD = adv[tid];
    int n0 = blockIdx.x*32;
    float acc[32];
    #pragma unroll
    for (int n=0;n<32;n++) acc[n]=0.f;
    for (int kc=0;kc<4;kc++){
        __syncthreads();
        for (int i=tid;i<4096;i+=128){
            int d=i>>5, k=i&31;
            sW[k*129+d] = lin[d*128 + kc*32 + k];
        }
        for (int i=tid;i<1024;i+=128){
            int n=i>>5, k=i&31;
            int node=n0+n;
            sIn[n*36+k] = (node<NN) ? g_h1[node*128 + kc*32 + k] : 0.f;
        }
        __syncthreads();
        #pragma unroll
        for (int k=0;k<32;k+=4){
            float w0=sW[(k+0)*129+tid], w1=sW[(k+1)*129+tid];
            float w2=sW[(k+2)*129+tid], w3=sW[(k+3)*129+tid];
            #pragma unroll
            for (int n=0;n<32;n++){
                float4 xv = *(const float4*)&sIn[n*36+k];
                acc[n] = fmaf(xv.x,w0, fmaf(xv.y,w1, fmaf(xv.z,w2, fmaf(xv.w,w3, acc[n]))));
            }
        }
    }
    int lane=tid&31, h=tid>>5;
    for (int n=0;n<32;n++){
        int node=n0+n;
        if (node>=NN) break;
        g_xs[node*128+tid] = acc[n];
        float s=acc[n]*attS, dd=acc[n]*attD;
        #pragma unroll
        for (int o=16;o>0;o>>=1){
            s  += __shfl_down_sync(0xffffffffu, s,  o);
            dd += __shfl_down_sync(0xffffffffu, dd, o);
        }
        if (lane==0){ g_asrc[node*4+h]=s; g_adst[node*4+h]=dd; }
    }
}

// ---------------- JK proj + classifier + log_softmax ----------------
__global__ void k_final(const float* __restrict__ jkw, const float* __restrict__ jkb,
                        const float* __restrict__ cw,  const float* __restrict__ cb,
                        float* __restrict__ out){
    __shared__ float sW[32*129];
    __shared__ __align__(16) float sIn[16*36];
    __shared__ float sT[16*129];
    int tid = threadIdx.x;
    int n0 = blockIdx.x*16;
    float bias = jkb[tid];
    float acc[16];
    #pragma unroll
    for (int n=0;n<16;n++) acc[n]=bias;
    for (int kc=0;kc<12;kc++){
        const float* src = (kc<4) ? g_h0 : (kc<8) ? g_h1 : g_h2;
        int off  = (kc&3)*32;
        int base = kc*32;
        __syncthreads();
        for (int i=tid;i<4096;i+=128){
            int d=i>>5, k=i&31;
            sW[k*129+d] = jkw[d*384 + base + k];
        }
        for (int i=tid;i<512;i+=128){
            int n=i>>5, k=i&31;
            int node=n0+n;
            sIn[n*36+k] = (node<NN) ? src[node*128 + off + k] : 0.f;
        }
        __syncthreads();
        #pragma unroll
        for (int k=0;k<32;k+=4){
            float w0=sW[(k+0)*129+tid], w1=sW[(k+1)*129+tid];
            float w2=sW[(k+2)*129+tid], w3=sW[(k+3)*129+tid];
            #pragma unroll
            for (int n=0;n<16;n++){
                float4 xv = *(const float4*)&sIn[n*36+k];
                acc[n] = fmaf(xv.x,w0, fmaf(xv.y,w1, fmaf(xv.z,w2, fmaf(xv.w,w3, acc[n]))));
            }
        }
    }
    __syncthreads();
    #pragma unroll
    for (int n=0;n<16;n++) sT[n*129+tid] = acc[n];
    __syncthreads();
    int lane = tid&31, w = tid>>5;
    for (int n=w;n<16;n+=4){
        int node = n0+n;
        if (node>=NN) continue;
        float lg[5];
        #pragma unroll
        for (int c=0;c<5;c++){
            float p = 0.f;
            #pragma unroll
            for (int j=0;j<4;j++){
                int d = lane + 32*j;
                p = fmaf(sT[n*129+d], cw[c*128+d], p);
            }
            #pragma unroll
            for (int o=16;o>0;o>>=1) p += __shfl_down_sync(0xffffffffu, p, o);
            lg[c] = p + cb[c];
        }
        if (lane==0){
            float m = lg[0];
            #pragma unroll
            for (int c=1;c<5;c++) m = fmaxf(m, lg[c]);
            float s = 0.f;
            #pragma unroll
            for (int c=0;c<5;c++) s += expf(lg[c]-m);
            float ls = logf(s);
            #pragma unroll
            for (int c=0;c<5;c++) out[node*5+c] = lg[c]-m-ls;
        }
    }
}

// ---------------- launcher ----------------
extern "C" void kernel_launch(void* const* d_in, const int* in_sizes, int n_in,
                              void* d_out, int out_size){
    const float* x      = (const float*)d_in[0];
    const int*   ei     = (const int*)  d_in[1];
    const float* ea     = (const float*)d_in[2];
    const float* ee_w1  = (const float*)d_in[3];
    const float* ee_b1  = (const float*)d_in[4];
    const float* ee_w2  = (const float*)d_in[5];
    const float* ee_b2  = (const float*)d_in[6];
    const float* proj_w = (const float*)d_in[7];
    const float* proj_b = (const float*)d_in[8];
    const float* c1_lin = (const float*)d_in[9];
    const float* c1_as  = (const float*)d_in[10];
    const float* c1_ad  = (const float*)d_in[11];
    const float* c1_le  = (const float*)d_in[12];
    const float* c1_ae  = (const float*)d_in[13];
    const float* c1_b   = (const float*)d_in[14];
    const float* c2_lin = (const float*)d_in[15];
    const float* c2_as  = (const float*)d_in[16];
    const float* c2_ad  = (const float*)d_in[17];
    const float* c2_le  = (const float*)d_in[18];
    const float* c2_ae  = (const float*)d_in[19];
    const float* c2_b   = (const float*)d_in[20];
    const float* n1_g   = (const float*)d_in[21];
    const float* n1_b   = (const float*)d_in[22];
    const float* n2_g   = (const float*)d_in[23];
    const float* n2_b   = (const float*)d_in[24];
    const float* jk_w   = (const float*)d_in[25];
    const float* jk_b   = (const float*)d_in[26];
    const float* cls_w  = (const float*)d_in[27];
    const float* cls_b  = (const float*)d_in[28];
    float* out = (float*)d_out;

    k_prep<<<1,32>>>(c1_le, c1_ae, c2_le, c2_ae);
    k_edge<<<(EE+255)/256,256>>>(ea, ee_w1, ee_b1, ee_w2, ee_b2);
    k_node1<<<(NN+15)/16,128>>>(x, proj_w, proj_b, c1_lin, c1_as, c1_ad);

    // conv1
    k_fill<<<512,256>>>();
    k_amax<<<(EE+255)/256,256>>>(ei, 0);
    k_asum<<<(EE+255)/256,256>>>(ei);
    k_msg<<<(EE*32+255)/256,256>>>(ei);
    k_epi<<<NN,128>>>(c1_b, n1_g, n1_b, 0);

    // conv2
    k_node2<<<(NN+31)/32,128>>>(c2_lin, c2_as, c2_ad);
    k_fill<<<512,256>>>();
    k_amax<<<(EE+255)/256,256>>>(ei, 1);
    k_asum<<<(EE+255)/256,256>>>(ei);
    k_msg<<<(EE*32+255)/256,256>>>(ei);
    k_epi<<<NN,128>>>(c2_b, n2_g, n2_b, 1);

    k_final<<<(NN+15)/16,128>>>(jk_w, jk_b, cls_w, cls_b, out);
}

// round 2
// speedup vs baseline: 1.8033x; 1.8033x over previous
#include <cuda_runtime.h>
#include <math.h>

#define NN 50000
#define EE 800000

// ---------------- scratch (device globals) ----------------
__device__ float g_ae1[EE*4];
__device__ float g_ae2[EE*4];
__device__ float g_sae1[EE*4];   // a_edge (conv1) permuted to CSR order
__device__ float g_sae2[EE*4];   // a_edge (conv2) permuted to CSR order
__device__ int   g_ssrc[EE];     // src node permuted to CSR order
__device__ int   g_cnt[NN];
__device__ int   g_cur[NN];
__device__ int   g_rowptr[NN+1];
__device__ float g_h0[NN*128];
__device__ float g_h1[NN*128];
__device__ float g_h2[NN*128];
__device__ float g_xs[NN*128];
__device__ float g_asrc[NN*4];
__device__ float g_adst[NN*4];
__device__ float g_M[32];        // [conv*16 + j*4 + h]
__device__ float g_CW[5*384];    // collapsed classifier: cls_w @ jk_w
__device__ float g_cb2[5];       // collapsed bias

// ---------------- precompute 4x4 edge-attention matrices ----------------
__global__ void k_prep(const float* le1, const float* ae1,
                       const float* le2, const float* ae2){
    int t = threadIdx.x;
    if (t >= 32) return;
    int which = t >> 4, j = (t >> 2) & 3, h = t & 3;
    const float* le = which ? le2 : le1;   // [128,4] row-major
    const float* ae = which ? ae2 : ae1;   // [4,32]  row-major
    float s = 0.f;
    for (int c = 0; c < 32; c++)
        s += le[(h*32+c)*4 + j] * ae[h*32+c];
    g_M[which*16 + j*4 + h] = s;
}

// ---------------- collapsed classifier weights ----------------
__global__ void k_prepcw(const float* __restrict__ cw, const float* __restrict__ cb,
                         const float* __restrict__ jkw, const float* __restrict__ jkb){
    int i = blockIdx.x*256 + threadIdx.x;
    if (i < 5*384){
        int c = i/384, j = i%384;
        float s = 0.f;
        for (int d = 0; d < 128; d++) s = fmaf(cw[c*128+d], jkw[d*384+j], s);
        g_CW[i] = s;
    } else if (i < 5*384+5){
        int c = i - 5*384;
        float s = cb[c];
        for (int d = 0; d < 128; d++) s = fmaf(cw[c*128+d], jkb[d], s);
        g_cb2[c] = s;
    }
}

// ---------------- CSR build ----------------
__global__ void k_zero(){
    int i = blockIdx.x*1024 + threadIdx.x;
    if (i < NN) g_cnt[i] = 0;
}

__global__ void k_hist(const int* __restrict__ ei){
    int e = blockIdx.x*1024 + threadIdx.x;
    if (e < EE) atomicAdd(&g_cnt[ei[EE+e]], 1);
}

__global__ void k_scan(){
    __shared__ int ssum[1024];
    int t = threadIdx.x;
    int beg = t*49, end = min(beg+49, NN);
    int s = 0;
    for (int i = beg; i < end; i++) s += g_cnt[i];
    ssum[t] = s;
    __syncthreads();
    for (int off = 1; off < 1024; off <<= 1){
        int v = (t >= off) ? ssum[t-off] : 0;
        __syncthreads();
        ssum[t] += v;
        __syncthreads();
    }
    int run = ssum[t] - s;   // exclusive prefix
    for (int i = beg; i < end; i++){
        g_rowptr[i] = run; g_cur[i] = run;
        run += g_cnt[i];
    }
    if (t == 1023) g_rowptr[NN] = ssum[1023];
}

__global__ void k_scatter(const int* __restrict__ ei){
    int e = blockIdx.x*256 + threadIdx.x;
    if (e >= EE) return;
    int s = ei[e], d = ei[EE+e];
    int pos = atomicAdd(&g_cur[d], 1);
    g_ssrc[pos] = s;
    ((float4*)g_sae1)[pos] = ((const float4*)g_ae1)[e];
    ((float4*)g_sae2)[pos] = ((const float4*)g_ae2)[e];
}

// ---------------- edge encoder fused with a_edge = e @ M ----------------
__global__ void k_edge(const float* __restrict__ ea,
                       const float* __restrict__ w1, const float* __restrict__ b1,
                       const float* __restrict__ w2, const float* __restrict__ b2){
    __shared__ float sw1[256], sb1[32], sw2[128], sb2[4], sM[32];
    int tid = threadIdx.x;
    if (tid < 256) sw1[tid] = w1[tid];
    if (tid < 32)  sb1[tid] = b1[tid];
    if (tid < 128) sw2[tid] = w2[tid];
    if (tid < 4)   sb2[tid] = b2[tid];
    if (tid >= 32 && tid < 64) sM[tid-32] = g_M[tid-32];
    __syncthreads();
    int e = blockIdx.x*256 + tid;
    if (e >= EE) return;
    float4 v0 = ((const float4*)ea)[e*2];
    float4 v1 = ((const float4*)ea)[e*2+1];
    float av[8] = {v0.x,v0.y,v0.z,v0.w,v1.x,v1.y,v1.z,v1.w};
    float e0=sb2[0], e1=sb2[1], e2=sb2[2], e3=sb2[3];
    #pragma unroll
    for (int c=0;c<32;c++){
        float hv = sb1[c];
        #pragma unroll
        for (int j=0;j<8;j++) hv = fmaf(sw1[c*8+j], av[j], hv);
        hv = fmaxf(hv, 0.f);
        e0 = fmaf(sw2[c],    hv, e0);
        e1 = fmaf(sw2[32+c], hv, e1);
        e2 = fmaf(sw2[64+c], hv, e2);
        e3 = fmaf(sw2[96+c], hv, e3);
    }
    float4 r1, r2;
    r1.x = e0*sM[0] + e1*sM[4] + e2*sM[8]  + e3*sM[12];
    r1.y = e0*sM[1] + e1*sM[5] + e2*sM[9]  + e3*sM[13];
    r1.z = e0*sM[2] + e1*sM[6] + e2*sM[10] + e3*sM[14];
    r1.w = e0*sM[3] + e1*sM[7] + e2*sM[11] + e3*sM[15];
    r2.x = e0*sM[16]+ e1*sM[20]+ e2*sM[24] + e3*sM[28];
    r2.y = e0*sM[17]+ e1*sM[21]+ e2*sM[25] + e3*sM[29];
    r2.z = e0*sM[18]+ e1*sM[22]+ e2*sM[26] + e3*sM[30];
    r2.w = e0*sM[19]+ e1*sM[23]+ e2*sM[27] + e3*sM[31];
    ((float4*)g_ae1)[e] = r1;
    ((float4*)g_ae2)[e] = r2;
}

// ---------------- conv1 node transforms: h0, xs1, a_src1, a_dst1 ----------------
__global__ void k_node1(const float* __restrict__ x,
                        const float* __restrict__ pw, const float* __restrict__ pb,
                        const float* __restrict__ lw,
                        const float* __restrict__ asv, const float* __restrict__ adv){
    __shared__ float sWp[16*129], sWl[16*129];
    __shared__ float sx[16*17];
    int tid = threadIdx.x;
    float attS = asv[tid], attD = adv[tid], pbd = pb[tid];
    for (int i=tid;i<2048;i+=128){
        int d=i>>4, k=i&15;
        sWp[k*129+d] = pw[i];
        sWl[k*129+d] = lw[i];
    }
    int n0 = blockIdx.x*16;
    for (int i=tid;i<256;i+=128){
        int n=i>>4, k=i&15;
        int node=n0+n;
        sx[n*17+k] = (node<NN) ? x[node*16+k] : 0.f;
    }
    __syncthreads();
    float acc0[16], acc1[16];
    #pragma unroll
    for (int n=0;n<16;n++){ acc0[n]=pbd; acc1[n]=0.f; }
    #pragma unroll
    for (int k=0;k<16;k++){
        float wp=sWp[k*129+tid], wl=sWl[k*129+tid];
        #pragma unroll
        for (int n=0;n<16;n++){
            float xv = sx[n*17+k];
            acc0[n] = fmaf(xv, wp, acc0[n]);
            acc1[n] = fmaf(xv, wl, acc1[n]);
        }
    }
    int lane = tid&31, h = tid>>5;
    for (int n=0;n<16;n++){
        int node=n0+n;
        if (node>=NN) break;
        g_h0[node*128+tid] = acc0[n];
        g_xs[node*128+tid] = acc1[n];
        float s = acc1[n]*attS, dd = acc1[n]*attD;
        #pragma unroll
        for (int o=16;o>0;o>>=1){
            s  += __shfl_down_sync(0xffffffffu, s, o);
            dd += __shfl_down_sync(0xffffffffu, dd, o);
        }
        if (lane==0){ g_asrc[node*4+h]=s; g_adst[node*4+h]=dd; }
    }
}

// ---------------- fused GAT conv: softmax + aggregate + ELU + residual + LN ----------------
__device__ __forceinline__ void gat_batch(int base, int cnt, int lane, int h, float4 ad,
                                          const float4* __restrict__ sae,
                                          const float4* __restrict__ asrc4,
                                          float4& den, float4& acc, bool full){
    int idx = base + lane;
    float4 w = make_float4(0.f,0.f,0.f,0.f);
    int s = 0;
    if (full || lane < cnt){
        s = g_ssrc[idx];
        float4 ae = sae[idx];
        float4 as = asrc4[s];
        float ax = as.x+ad.x+ae.x; ax = ax>0.f?ax:0.2f*ax;
        float ay = as.y+ad.y+ae.y; ay = ay>0.f?ay:0.2f*ay;
        float az = as.z+ad.z+ae.z; az = az>0.f?az:0.2f*az;
        float aw = as.w+ad.w+ae.w; aw = aw>0.f?aw:0.2f*aw;
        w = make_float4(__expf(ax), __expf(ay), __expf(az), __expf(aw));
    }
    den.x += w.x; den.y += w.y; den.z += w.z; den.w += w.w;
    if (full){
        #pragma unroll
        for (int j=0;j<32;j++){
            int   sj = __shfl_sync(0xffffffffu, s, j);
            float wx = __shfl_sync(0xffffffffu, w.x, j);
            float wy = __shfl_sync(0xffffffffu, w.y, j);
            float wz = __shfl_sync(0xffffffffu, w.z, j);
            float ww = __shfl_sync(0xffffffffu, w.w, j);
            float wj = (h==0)?wx:(h==1)?wy:(h==2)?wz:ww;
            float4 xv = ((const float4*)g_xs)[sj*32 + lane];
            acc.x = fmaf(wj, xv.x, acc.x);
            acc.y = fmaf(wj, xv.y, acc.y);
            acc.z = fmaf(wj, xv.z, acc.z);
            acc.w = fmaf(wj, xv.w, acc.w);
        }
    } else {
        for (int j=0;j<cnt;j++){
            int   sj = __shfl_sync(0xffffffffu, s, j);
            float wx = __shfl_sync(0xffffffffu, w.x, j);
            float wy = __shfl_sync(0xffffffffu, w.y, j);
            float wz = __shfl_sync(0xffffffffu, w.z, j);
            float ww = __shfl_sync(0xffffffffu, w.w, j);
            float wj = (h==0)?wx:(h==1)?wy:(h==2)?wz:ww;
            float4 xv = ((const float4*)g_xs)[sj*32 + lane];
            acc.x = fmaf(wj, xv.x, acc.x);
            acc.y = fmaf(wj, xv.y, acc.y);
            acc.z = fmaf(wj, xv.z, acc.z);
            acc.w = fmaf(wj, xv.w, acc.w);
        }
    }
}

__global__ void k_gat(const float* __restrict__ bias, const float* __restrict__ gam,
                      const float* __restrict__ bet, int conv){
    int node = blockIdx.x*8 + (threadIdx.x>>5);
    if (node >= NN) return;
    int lane = threadIdx.x & 31;
    int h = lane >> 3;
    const float4* sae   = (const float4*)(conv ? g_sae2 : g_sae1);
    const float4* asrc4 = (const float4*)g_asrc;
    float4 ad = ((const float4*)g_adst)[node];
    int beg = g_rowptr[node], end = g_rowptr[node+1];
    float4 den = make_float4(0.f,0.f,0.f,0.f);
    float4 acc = make_float4(0.f,0.f,0.f,0.f);
    int base = beg;
    for (; base + 32 <= end; base += 32)
        gat_batch(base, 32, lane, h, ad, sae, asrc4, den, acc, true);
    if (base < end)
        gat_batch(base, end-base, lane, h, ad, sae, asrc4, den, acc, false);
    // reduce denominator across warp (per head)
    #pragma unroll
    for (int o=16;o>0;o>>=1){
        den.x += __shfl_xor_sync(0xffffffffu, den.x, o);
        den.y += __shfl_xor_sync(0xffffffffu, den.y, o);
        den.z += __shfl_xor_sync(0xffffffffu, den.z, o);
        den.w += __shfl_xor_sync(0xffffffffu, den.w, o);
    }
    float dh = (h==0)?den.x:(h==1)?den.y:(h==2)?den.z:den.w;
    float inv = 1.f/(dh + 1e-16f);
    // epilogue: bias + ELU + residual + layernorm
    const float* hp = conv ? g_h1 : g_h0;
    float*       ho = conv ? g_h2 : g_h1;
    float4 hv = ((const float4*)hp)[node*32+lane];
    float4 bv = *(const float4*)&bias[lane*4];
    float4 r;
    r.x = acc.x*inv + bv.x; r.x = (r.x>0.f)?r.x:(__expf(r.x)-1.f); r.x += hv.x;
    r.y = acc.y*inv + bv.y; r.y = (r.y>0.f)?r.y:(__expf(r.y)-1.f); r.y += hv.y;
    r.z = acc.z*inv + bv.z; r.z = (r.z>0.f)?r.z:(__expf(r.z)-1.f); r.z += hv.z;
    r.w = acc.w*inv + bv.w; r.w = (r.w>0.f)?r.w:(__expf(r.w)-1.f); r.w += hv.w;
    float s1 = r.x+r.y+r.z+r.w;
    float s2 = r.x*r.x + r.y*r.y + r.z*r.z + r.w*r.w;
    #pragma unroll
    for (int o=16;o>0;o>>=1){
        s1 += __shfl_xor_sync(0xffffffffu, s1, o);
        s2 += __shfl_xor_sync(0xffffffffu, s2, o);
    }
    float mu  = s1 * (1.f/128.f);
    float var = s2 * (1.f/128.f) - mu*mu;
    float rs  = rsqrtf(var + 1e-5f);
    float4 gv = *(const float4*)&gam[lane*4];
    float4 be = *(const float4*)&bet[lane*4];
    float4 o4;
    o4.x = (r.x-mu)*rs*gv.x + be.x;
    o4.y = (r.y-mu)*rs*gv.y + be.y;
    o4.z = (r.z-mu)*rs*gv.z + be.z;
    o4.w = (r.w-mu)*rs*gv.w + be.w;
    ((float4*)ho)[node*32+lane] = o4;
}

// ---------------- conv2 GEMM: xs = h1 @ c2_lin^T (50000x128x128) ----------------
__global__ void k_node2(const float* __restrict__ lin){
    __shared__ float sA[16*65];
    __shared__ float sB[16*132];
    int tid = threadIdx.x;
    int tx = tid & 31, ty = tid >> 5;
    int n0 = blockIdx.x*64;
    float acc[8][4];
    #pragma unroll
    for (int r=0;r<8;r++){ acc[r][0]=0.f; acc[r][1]=0.f; acc[r][2]=0.f; acc[r][3]=0.f; }
    for (int kc=0;kc<8;kc++){
        __syncthreads();
        {   // A tile: 64 rows x 16 cols
            int r = tid>>2, q = tid&3;
            int node = n0 + r;
            float4 v = (node<NN) ? *(const float4*)&g_h1[node*128 + kc*16 + q*4]
                                 : make_float4(0.f,0.f,0.f,0.f);
            sA[(q*4+0)*65+r]=v.x; sA[(q*4+1)*65+r]=v.y;
            sA[(q*4+2)*65+r]=v.z; sA[(q*4+3)*65+r]=v.w;
        }
        {   // B tile: 16 k x 128 d, from lin[d*128+k]
            int d = tid>>1;
            int kq = (tid&1)*8;
            #pragma unroll
            for (int p=0;p<2;p++){
                float4 v = *(const float4*)&lin[d*128 + kc*16 + kq + p*4];
                sB[(kq+p*4+0)*132+d]=v.x; sB[(kq+p*4+1)*132+d]=v.y;
                sB[(kq+p*4+2)*132+d]=v.z; sB[(kq+p*4+3)*132+d]=v.w;
            }
        }
        __syncthreads();
        #pragma unroll
        for (int k=0;k<16;k++){
            float4 b = *(const float4*)&sB[k*132 + tx*4];
            #pragma unroll
            for (int r=0;r<8;r++){
                float a = sA[k*65 + ty*8 + r];
                acc[r][0]=fmaf(a,b.x,acc[r][0]);
                acc[r][1]=fmaf(a,b.y,acc[r][1]);
                acc[r][2]=fmaf(a,b.z,acc[r][2]);
                acc[r][3]=fmaf(a,b.w,acc[r][3]);
            }
        }
    }
    #pragma unroll
    for (int r=0;r<8;r++){
        int node = n0 + ty*8 + r;
        if (node < NN){
            float4 v = make_float4(acc[r][0],acc[r][1],acc[r][2],acc[r][3]);
            *(float4*)&g_xs[node*128 + tx*4] = v;
        }
    }
}

// ---------------- conv2 attention dots ----------------
__global__ void k_att2(const float* __restrict__ asv, const float* __restrict__ adv){
    int node = blockIdx.x*8 + (threadIdx.x>>5);
    if (node >= NN) return;
    int lane = threadIdx.x & 31;
    int h = lane >> 3;
    float4 xv = ((const float4*)g_xs)[node*32+lane];
    float4 ws = *(const float4*)&asv[lane*4];
    float4 wd = *(const float4*)&adv[lane*4];
    float s = xv.x*ws.x + xv.y*ws.y + xv.z*ws.z + xv.w*ws.w;
    float d = xv.x*wd.x + xv.y*wd.y + xv.z*wd.z + xv.w*wd.w;
    #pragma unroll
    for (int o=1;o<8;o<<=1){
        s += __shfl_xor_sync(0xffffffffu, s, o);
        d += __shfl_xor_sync(0xffffffffu, d, o);
    }
    if ((lane&7)==0){ g_asrc[node*4+h]=s; g_adst[node*4+h]=d; }
}

// ---------------- collapsed output: logits + log_softmax ----------------
__global__ void k_out(float* __restrict__ out){
    __shared__ float sCW[5*384];
    __shared__ float sCB[5];
    int tid = threadIdx.x;
    for (int i=tid;i<1920;i+=256) sCW[i] = g_CW[i];
    if (tid < 5) sCB[tid] = g_cb2[tid];
    __syncthreads();
    int node = blockIdx.x*8 + (tid>>5);
    if (node >= NN) return;
    int lane = tid & 31;
    float4 a0 = ((const float4*)g_h0)[node*32+lane];
    float4 a1 = ((const float4*)g_h1)[node*32+lane];
    float4 a2 = ((const float4*)g_h2)[node*32+lane];
    float lg[5];
    #pragma unroll
    for (int c=0;c<5;c++){
        const float* w = &sCW[c*384];
        float4 b0 = *(const float4*)&w[lane*4];
        float4 b1 = *(const float4*)&w[128 + lane*4];
        float4 b2 = *(const float4*)&w[256 + lane*4];
        float p = a0.x*b0.x + a0.y*b0.y + a0.z*b0.z + a0.w*b0.w;
        p = fmaf(a1.x,b1.x, fmaf(a1.y,b1.y, fmaf(a1.z,b1.z, fmaf(a1.w,b1.w, p))));
        p = fmaf(a2.x,b2.x, fmaf(a2.y,b2.y, fmaf(a2.z,b2.z, fmaf(a2.w,b2.w, p))));
        #pragma unroll
        for (int o=16;o>0;o>>=1) p += __shfl_xor_sync(0xffffffffu, p, o);
        lg[c] = p + sCB[c];
    }
    if (lane == 0){
        float m = lg[0];
        #pragma unroll
        for (int c=1;c<5;c++) m = fmaxf(m, lg[c]);
        float s = 0.f;
        #pragma unroll
        for (int c=0;c<5;c++) s += __expf(lg[c]-m);
        float ls = logf(s);
        #pragma unroll
        for (int c=0;c<5;c++) out[node*5+c] = lg[c]-m-ls;
    }
}

// ---------------- launcher ----------------
extern "C" void kernel_launch(void* const* d_in, const int* in_sizes, int n_in,
                              void* d_out, int out_size){
    const float* x      = (const float*)d_in[0];
    const int*   ei     = (const int*)  d_in[1];
    const float* ea     = (const float*)d_in[2];
    const float* ee_w1  = (const float*)d_in[3];
    const float* ee_b1  = (const float*)d_in[4];
    const float* ee_w2  = (const float*)d_in[5];
    const float* ee_b2  = (const float*)d_in[6];
    const float* proj_w = (const float*)d_in[7];
    const float* proj_b = (const float*)d_in[8];
    const float* c1_lin = (const float*)d_in[9];
    const float* c1_as  = (const float*)d_in[10];
    const float* c1_ad  = (const float*)d_in[11];
    const float* c1_le  = (const float*)d_in[12];
    const float* c1_ae  = (const float*)d_in[13];
    const float* c1_b   = (const float*)d_in[14];
    const float* c2_lin = (const float*)d_in[15];
    const float* c2_as  = (const float*)d_in[16];
    const float* c2_ad  = (const float*)d_in[17];
    const float* c2_le  = (const float*)d_in[18];
    const float* c2_ae  = (const float*)d_in[19];
    const float* c2_b   = (const float*)d_in[20];
    const float* n1_g   = (const float*)d_in[21];
    const float* n1_b   = (const float*)d_in[22];
    const float* n2_g   = (const float*)d_in[23];
    const float* n2_b   = (const float*)d_in[24];
    const float* jk_w   = (const float*)d_in[25];
    const float* jk_b   = (const float*)d_in[26];
    const float* cls_w  = (const float*)d_in[27];
    const float* cls_b  = (const float*)d_in[28];
    float* out = (float*)d_out;

    k_prep<<<1,32>>>(c1_le, c1_ae, c2_le, c2_ae);
    k_prepcw<<<8,256>>>(cls_w, cls_b, jk_w, jk_b);
    k_zero<<<49,1024>>>();
    k_hist<<<(EE+1023)/1024,1024>>>(ei);
    k_edge<<<(EE+255)/256,256>>>(ea, ee_w1, ee_b1, ee_w2, ee_b2);
    k_scan<<<1,1024>>>();
    k_scatter<<<(EE+255)/256,256>>>(ei);
    k_node1<<<(NN+15)/16,128>>>(x, proj_w, proj_b, c1_lin, c1_as, c1_ad);

    // conv1 (fused softmax + aggregate + ELU + residual + LN)
    k_gat<<<(NN+7)/8,256>>>(c1_b, n1_g, n1_b, 0);

    // conv2
    k_node2<<<(NN+63)/64,256>>>(c2_lin);
    k_att2<<<(NN+7)/8,256>>>(c2_as, c2_ad);
    k_gat<<<(NN+7)/8,256>>>(c2_b, n2_g, n2_b, 1);

    // collapsed JK+classifier+log_softmax
    k_out<<<(NN+7)/8,256>>>(out);
}

// round 3
// speedup vs baseline: 1.9991x; 1.1086x over previous
#include <cuda_runtime.h>
#include <math.h>

#define NN 50000
#define EE 800000

// ---------------- scratch (device globals) ----------------
__device__ float g_sae1[EE*4];   // a_edge (conv1) in CSR order
__device__ float g_sae2[EE*4];   // a_edge (conv2) in CSR order
__device__ int   g_ssrc[EE];     // src node in CSR order
__device__ int   g_cnt[NN];
__device__ int   g_cur[NN];
__device__ int   g_rowptr[NN+1];
__device__ float g_h0[NN*128];
__device__ float g_h1[NN*128];
__device__ float g_h2[NN*128];
__device__ float g_xs[NN*128];
__device__ float g_asrc[NN*4];
__device__ float g_adst[NN*4];
__device__ float g_M[32];        // [conv*16 + j*4 + h]
__device__ float g_CW[5*384];    // collapsed classifier: cls_w @ jk_w
__device__ float g_cb2[5];       // collapsed bias

// ---------------- packed f32x2 helpers ----------------
__device__ __forceinline__ unsigned long long pack2(float x){
    unsigned long long r;
    unsigned int u = __float_as_uint(x);
    asm("mov.b64 %0, {%1, %1};" : "=l"(r) : "r"(u));
    return r;
}
__device__ __forceinline__ void fma2(unsigned long long& acc,
                                     unsigned long long a, unsigned long long b){
    asm("fma.rn.f32x2 %0, %1, %2, %0;" : "+l"(acc) : "l"(a), "l"(b));
}

// ---------------- precompute 4x4 edge-attention matrices ----------------
__global__ void k_prep(const float* le1, const float* ae1,
                       const float* le2, const float* ae2){
    int t = threadIdx.x;
    if (t >= 32) return;
    int which = t >> 4, j = (t >> 2) & 3, h = t & 3;
    const float* le = which ? le2 : le1;   // [128,4] row-major
    const float* ae = which ? ae2 : ae1;   // [4,32]  row-major
    float s = 0.f;
    for (int c = 0; c < 32; c++)
        s += le[(h*32+c)*4 + j] * ae[h*32+c];
    g_M[which*16 + j*4 + h] = s;
}

// ---------------- collapsed classifier weights ----------------
__global__ void k_prepcw(const float* __restrict__ cw, const float* __restrict__ cb,
                         const float* __restrict__ jkw, const float* __restrict__ jkb){
    int i = blockIdx.x*256 + threadIdx.x;
    if (i < 5*384){
        int c = i/384, j = i%384;
        float s = 0.f;
        for (int d = 0; d < 128; d++) s = fmaf(cw[c*128+d], jkw[d*384+j], s);
        g_CW[i] = s;
    } else if (i < 5*384+5){
        int c = i - 5*384;
        float s = cb[c];
        for (int d = 0; d < 128; d++) s = fmaf(cw[c*128+d], jkb[d], s);
        g_cb2[c] = s;
    }
}

// ---------------- CSR build ----------------
__global__ void k_zero(){
    int i = blockIdx.x*1024 + threadIdx.x;
    if (i < NN) g_cnt[i] = 0;
}

__global__ void k_hist(const int* __restrict__ ei){
    int e = blockIdx.x*1024 + threadIdx.x;
    if (e < EE) atomicAdd(&g_cnt[ei[EE+e]], 1);
}

__global__ void k_scan(){
    __shared__ int ssum[1024];
    int t = threadIdx.x;
    int beg = t*49, end = min(beg+49, NN);
    int s = 0;
    for (int i = beg; i < end; i++) s += g_cnt[i];
    ssum[t] = s;
    __syncthreads();
    for (int off = 1; off < 1024; off <<= 1){
        int v = (t >= off) ? ssum[t-off] : 0;
        __syncthreads();
        ssum[t] += v;
        __syncthreads();
    }
    int run = ssum[t] - s;   // exclusive prefix
    for (int i = beg; i < end; i++){
        g_rowptr[i] = run; g_cur[i] = run;
        run += g_cnt[i];
    }
    if (t == 1023) g_rowptr[NN] = ssum[1023];
}

// ---------------- edge encoder + a_edge + CSR scatter (fused) ----------------
__global__ void k_edge(const float* __restrict__ ea, const int* __restrict__ ei,
                       const float* __restrict__ w1, const float* __restrict__ b1,
                       const float* __restrict__ w2, const float* __restrict__ b2){
    __shared__ float sw1[256], sb1[32], sw2[128], sb2[4], sM[32];
    int tid = threadIdx.x;
    if (tid < 256) sw1[tid] = w1[tid];
    if (tid < 32)  sb1[tid] = b1[tid];
    if (tid < 128) sw2[tid] = w2[tid];
    if (tid < 4)   sb2[tid] = b2[tid];
    if (tid >= 32 && tid < 64) sM[tid-32] = g_M[tid-32];
    __syncthreads();
    int e = blockIdx.x*256 + tid;
    if (e >= EE) return;
    float4 v0 = ((const float4*)ea)[e*2];
    float4 v1 = ((const float4*)ea)[e*2+1];
    float av[8] = {v0.x,v0.y,v0.z,v0.w,v1.x,v1.y,v1.z,v1.w};
    float e0=sb2[0], e1=sb2[1], e2=sb2[2], e3=sb2[3];
    #pragma unroll
    for (int c=0;c<32;c++){
        float hv = sb1[c];
        #pragma unroll
        for (int j=0;j<8;j++) hv = fmaf(sw1[c*8+j], av[j], hv);
        hv = fmaxf(hv, 0.f);
        e0 = fmaf(sw2[c],    hv, e0);
        e1 = fmaf(sw2[32+c], hv, e1);
        e2 = fmaf(sw2[64+c], hv, e2);
        e3 = fmaf(sw2[96+c], hv, e3);
    }
    float4 r1, r2;
    r1.x = e0*sM[0] + e1*sM[4] + e2*sM[8]  + e3*sM[12];
    r1.y = e0*sM[1] + e1*sM[5] + e2*sM[9]  + e3*sM[13];
    r1.z = e0*sM[2] + e1*sM[6] + e2*sM[10] + e3*sM[14];
    r1.w = e0*sM[3] + e1*sM[7] + e2*sM[11] + e3*sM[15];
    r2.x = e0*sM[16]+ e1*sM[20]+ e2*sM[24] + e3*sM[28];
    r2.y = e0*sM[17]+ e1*sM[21]+ e2*sM[25] + e3*sM[29];
    r2.z = e0*sM[18]+ e1*sM[22]+ e2*sM[26] + e3*sM[30];
    r2.w = e0*sM[19]+ e1*sM[23]+ e2*sM[27] + e3*sM[31];
    int srcn = ei[e], d = ei[EE+e];
    int pos = atomicAdd(&g_cur[d], 1);
    g_ssrc[pos] = srcn;
    ((float4*)g_sae1)[pos] = r1;
    ((float4*)g_sae2)[pos] = r2;
}

// ---------------- conv1 node transforms: h0, xs1, a_src1, a_dst1 ----------------
__global__ void k_node1(const float* __restrict__ x,
                        const float* __restrict__ pw, const float* __restrict__ pb,
                        const float* __restrict__ lw,
                        const float* __restrict__ asv, const float* __restrict__ adv){
    __shared__ float sWp[16*129], sWl[16*129];
    __shared__ float sx[16*17];
    int tid = threadIdx.x;
    float attS = asv[tid], attD = adv[tid], pbd = pb[tid];
    for (int i=tid;i<2048;i+=128){
        int d=i>>4, k=i&15;
        sWp[k*129+d] = pw[i];
        sWl[k*129+d] = lw[i];
    }
    int n0 = blockIdx.x*16;
    for (int i=tid;i<256;i+=128){
        int n=i>>4, k=i&15;
        int node=n0+n;
        sx[n*17+k] = (node<NN) ? x[node*16+k] : 0.f;
    }
    __syncthreads();
    float acc0[16], acc1[16];
    #pragma unroll
    for (int n=0;n<16;n++){ acc0[n]=pbd; acc1[n]=0.f; }
    #pragma unroll
    for (int k=0;k<16;k++){
        float wp=sWp[k*129+tid], wl=sWl[k*129+tid];
        #pragma unroll
        for (int n=0;n<16;n++){
            float xv = sx[n*17+k];
            acc0[n] = fmaf(xv, wp, acc0[n]);
            acc1[n] = fmaf(xv, wl, acc1[n]);
        }
    }
    int lane = tid&31, h = tid>>5;
    for (int n=0;n<16;n++){
        int node=n0+n;
        if (node>=NN) break;
        g_h0[node*128+tid] = acc0[n];
        g_xs[node*128+tid] = acc1[n];
        float s = acc1[n]*attS, dd = acc1[n]*attD;
        #pragma unroll
        for (int o=16;o>0;o>>=1){
            s  += __shfl_down_sync(0xffffffffu, s, o);
            dd += __shfl_down_sync(0xffffffffu, dd, o);
        }
        if (lane==0){ g_asrc[node*4+h]=s; g_adst[node*4+h]=dd; }
    }
}

// ---------------- fused GAT conv: softmax + aggregate + ELU + residual + LN ----------------
__global__ void __launch_bounds__(512) k_gat(const float* __restrict__ bias,
                      const float* __restrict__ gam,
                      const float* __restrict__ bet, int conv){
    __shared__ float sw[16][128];
    __shared__ int   ss[16][32];
    int wid = threadIdx.x >> 5, lane = threadIdx.x & 31;
    int node = blockIdx.x*16 + wid;
    if (node >= NN) return;
    int h = lane >> 3;
    const float4* sae   = (const float4*)(conv ? g_sae2 : g_sae1);
    const float4* asrc4 = (const float4*)g_asrc;
    float4 ad = ((const float4*)g_adst)[node];
    int beg = g_rowptr[node], end = g_rowptr[node+1];
    float4 den = make_float4(0.f,0.f,0.f,0.f);
    float4 acc = make_float4(0.f,0.f,0.f,0.f);
    for (int base = beg; base < end; base += 32){
        int idx = base + lane;
        bool v = idx < end;
        int s = g_ssrc[v ? idx : end-1];
        float4 w = make_float4(0.f,0.f,0.f,0.f);
        if (v){
            float4 ae = sae[idx];
            float4 as = asrc4[s];
            float ax = as.x+ad.x+ae.x; ax = ax>0.f?ax:0.2f*ax;
            float ay = as.y+ad.y+ae.y; ay = ay>0.f?ay:0.2f*ay;
            float az = as.z+ad.z+ae.z; az = az>0.f?az:0.2f*az;
            float aw = as.w+ad.w+ae.w; aw = aw>0.f?aw:0.2f*aw;
            w = make_float4(__expf(ax), __expf(ay), __expf(az), __expf(aw));
        }
        den.x += w.x; den.y += w.y; den.z += w.z; den.w += w.w;
        __syncwarp();
        ss[wid][lane] = s;
        ((float4*)sw[wid])[lane] = w;
        __syncwarp();
        #pragma unroll
        for (int j=0;j<32;j++){
            int   sj = ss[wid][j];
            float wj = sw[wid][j*4 + h];
            float4 xv = ((const float4*)g_xs)[sj*32 + lane];
            acc.x = fmaf(wj, xv.x, acc.x);
            acc.y = fmaf(wj, xv.y, acc.y);
            acc.z = fmaf(wj, xv.z, acc.z);
            acc.w = fmaf(wj, xv.w, acc.w);
        }
    }
    // reduce denominator across warp (per head)
    #pragma unroll
    for (int o=16;o>0;o>>=1){
        den.x += __shfl_xor_sync(0xffffffffu, den.x, o);
        den.y += __shfl_xor_sync(0xffffffffu, den.y, o);
        den.z += __shfl_xor_sync(0xffffffffu, den.z, o);
        den.w += __shfl_xor_sync(0xffffffffu, den.w, o);
    }
    float dh = (h==0)?den.x:(h==1)?den.y:(h==2)?den.z:den.w;
    float inv = 1.f/(dh + 1e-16f);
    // epilogue: bias + ELU + residual + layernorm
    const float* hp = conv ? g_h1 : g_h0;
    float*       ho = conv ? g_h2 : g_h1;
    float4 hv = ((const float4*)hp)[node*32+lane];
    float4 bv = *(const float4*)&bias[lane*4];
    float4 r;
    r.x = acc.x*inv + bv.x; r.x = (r.x>0.f)?r.x:(__expf(r.x)-1.f); r.x += hv.x;
    r.y = acc.y*inv + bv.y; r.y = (r.y>0.f)?r.y:(__expf(r.y)-1.f); r.y += hv.y;
    r.z = acc.z*inv + bv.z; r.z = (r.z>0.f)?r.z:(__expf(r.z)-1.f); r.z += hv.z;
    r.w = acc.w*inv + bv.w; r.w = (r.w>0.f)?r.w:(__expf(r.w)-1.f); r.w += hv.w;
    float s1 = r.x+r.y+r.z+r.w;
    float s2 = r.x*r.x + r.y*r.y + r.z*r.z + r.w*r.w;
    #pragma unroll
    for (int o=16;o>0;o>>=1){
        s1 += __shfl_xor_sync(0xffffffffu, s1, o);
        s2 += __shfl_xor_sync(0xffffffffu, s2, o);
    }
    float mu  = s1 * (1.f/128.f);
    float var = s2 * (1.f/128.f) - mu*mu;
    float rs  = rsqrtf(var + 1e-5f);
    float4 gv = *(const float4*)&gam[lane*4];
    float4 be = *(const float4*)&bet[lane*4];
    float4 o4;
    o4.x = (r.x-mu)*rs*gv.x + be.x;
    o4.y = (r.y-mu)*rs*gv.y + be.y;
    o4.z = (r.z-mu)*rs*gv.z + be.z;
    o4.w = (r.w-mu)*rs*gv.w + be.w;
    ((float4*)ho)[node*32+lane] = o4;
}

// ---------------- conv2 GEMM: xs = h1 @ c2_lin^T via packed f32x2 FMA ----------------
__global__ void __launch_bounds__(256) k_node2(const float* __restrict__ lin){
    __shared__ float sA[16*132];
    __shared__ float sB[16*132];
    int tid = threadIdx.x;
    int tx = tid & 15, ty = tid >> 4;
    int n0 = blockIdx.x*128;
    unsigned long long acc[8][4];
    #pragma unroll
    for (int r=0;r<8;r++)
        #pragma unroll
        for (int p=0;p<4;p++) acc[r][p] = 0ULL;
    for (int kc=0;kc<8;kc++){
        __syncthreads();
        #pragma unroll
        for (int t=tid;t<512;t+=256){
            int r = t>>2, q = t&3;
            int node = n0 + r;
            float4 v = (node<NN) ? *(const float4*)&g_h1[node*128 + kc*16 + q*4]
                                 : make_float4(0.f,0.f,0.f,0.f);
            sA[(q*4+0)*132+r]=v.x; sA[(q*4+1)*132+r]=v.y;
            sA[(q*4+2)*132+r]=v.z; sA[(q*4+3)*132+r]=v.w;
        }
        #pragma unroll
        for (int t=tid;t<512;t+=256){
            int d = t>>2, q = t&3;
            float4 v = *(const float4*)&lin[d*128 + kc*16 + q*4];
            sB[(q*4+0)*132+d]=v.x; sB[(q*4+1)*132+d]=v.y;
            sB[(q*4+2)*132+d]=v.z; sB[(q*4+3)*132+d]=v.w;
        }
        __syncthreads();
        #pragma unroll
        for (int k=0;k<16;k++){
            float4 a0 = *(const float4*)&sA[k*132 + ty*8];
            float4 a1 = *(const float4*)&sA[k*132 + ty*8 + 4];
            ulonglong2 b0 = *(const ulonglong2*)&sB[k*132 + tx*8];
            ulonglong2 b1 = *(const ulonglong2*)&sB[k*132 + tx*8 + 4];
            unsigned long long bp0=b0.x, bp1=b0.y, bp2=b1.x, bp3=b1.y;
            float ar[8] = {a0.x,a0.y,a0.z,a0.w,a1.x,a1.y,a1.z,a1.w};
            #pragma unroll
            for (int r=0;r<8;r++){
                unsigned long long a2 = pack2(ar[r]);
                fma2(acc[r][0], a2, bp0);
                fma2(acc[r][1], a2, bp1);
                fma2(acc[r][2], a2, bp2);
                fma2(acc[r][3], a2, bp3);
            }
        }
    }
    #pragma unroll
    for (int r=0;r<8;r++){
        int node = n0 + ty*8 + r;
        if (node < NN){
            ulonglong2 v0; v0.x = acc[r][0]; v0.y = acc[r][1];
            ulonglong2 v1; v1.x = acc[r][2]; v1.y = acc[r][3];
            *(ulonglong2*)&g_xs[node*128 + tx*8]     = v0;
            *(ulonglong2*)&g_xs[node*128 + tx*8 + 4] = v1;
        }
    }
}

// ---------------- conv2 attention dots ----------------
__global__ void k_att2(const float* __restrict__ asv, const float* __restrict__ adv){
    int node = blockIdx.x*8 + (threadIdx.x>>5);
    if (node >= NN) return;
    int lane = threadIdx.x & 31;
    int h = lane >> 3;
    float4 xv = ((const float4*)g_xs)[node*32+lane];
    float4 ws = *(const float4*)&asv[lane*4];
    float4 wd = *(const float4*)&adv[lane*4];
    float s = xv.x*ws.x + xv.y*ws.y + xv.z*ws.z + xv.w*ws.w;
    float d = xv.x*wd.x + xv.y*wd.y + xv.z*wd.z + xv.w*wd.w;
    #pragma unroll
    for (int o=1;o<8;o<<=1){
        s += __shfl_xor_sync(0xffffffffu, s, o);
        d += __shfl_xor_sync(0xffffffffu, d, o);
    }
    if ((lane&7)==0){ g_asrc[node*4+h]=s; g_adst[node*4+h]=d; }
}

// ---------------- collapsed output: logits + log_softmax ----------------
__global__ void k_out(float* __restrict__ out){
    __shared__ float sCW[5*384];
    __shared__ float sCB[5];
    int tid = threadIdx.x;
    for (int i=tid;i<1920;i+=256) sCW[i] = g_CW[i];
    if (tid < 5) sCB[tid] = g_cb2[tid];
    __syncthreads();
    int node = blockIdx.x*8 + (tid>>5);
    if (node >= NN) return;
    int lane = tid & 31;
    float4 a0 = ((const float4*)g_h0)[node*32+lane];
    float4 a1 = ((const float4*)g_h1)[node*32+lane];
    float4 a2 = ((const float4*)g_h2)[node*32+lane];
    float lg[5];
    #pragma unroll
    for (int c=0;c<5;c++){
        const float* w = &sCW[c*384];
        float4 b0 = *(const float4*)&w[lane*4];
        float4 b1 = *(const float4*)&w[128 + lane*4];
        float4 b2 = *(const float4*)&w[256 + lane*4];
        float p = a0.x*b0.x + a0.y*b0.y + a0.z*b0.z + a0.w*b0.w;
        p = fmaf(a1.x,b1.x, fmaf(a1.y,b1.y, fmaf(a1.z,b1.z, fmaf(a1.w,b1.w, p))));
        p = fmaf(a2.x,b2.x, fmaf(a2.y,b2.y, fmaf(a2.z,b2.z, fmaf(a2.w,b2.w, p))));
        #pragma unroll
        for (int o=16;o>0;o>>=1) p += __shfl_xor_sync(0xffffffffu, p, o);
        lg[c] = p + sCB[c];
    }
    if (lane == 0){
        float m = lg[0];
        #pragma unroll
        for (int c=1;c<5;c++) m = fmaxf(m, lg[c]);
        float s = 0.f;
        #pragma unroll
        for (int c=0;c<5;c++) s += __expf(lg[c]-m);
        float ls = logf(s);
        #pragma unroll
        for (int c=0;c<5;c++) out[node*5+c] = lg[c]-m-ls;
    }
}

// ---------------- launcher ----------------
extern "C" void kernel_launch(void* const* d_in, const int* in_sizes, int n_in,
                              void* d_out, int out_size){
    const float* x      = (const float*)d_in[0];
    const int*   ei     = (const int*)  d_in[1];
    const float* ea     = (const float*)d_in[2];
    const float* ee_w1  = (const float*)d_in[3];
    const float* ee_b1  = (const float*)d_in[4];
    const float* ee_w2  = (const float*)d_in[5];
    const float* ee_b2  = (const float*)d_in[6];
    const float* proj_w = (const float*)d_in[7];
    const float* proj_b = (const float*)d_in[8];
    const float* c1_lin = (const float*)d_in[9];
    const float* c1_as  = (const float*)d_in[10];
    const float* c1_ad  = (const float*)d_in[11];
    const float* c1_le  = (const float*)d_in[12];
    const float* c1_ae  = (const float*)d_in[13];
    const float* c1_b   = (const float*)d_in[14];
    const float* c2_lin = (const float*)d_in[15];
    const float* c2_as  = (const float*)d_in[16];
    const float* c2_ad  = (const float*)d_in[17];
    const float* c2_le  = (const float*)d_in[18];
    const float* c2_ae  = (const float*)d_in[19];
    const float* c2_b   = (const float*)d_in[20];
    const float* n1_g   = (const float*)d_in[21];
    const float* n1_b   = (const float*)d_in[22];
    const float* n2_g   = (const float*)d_in[23];
    const float* n2_b   = (const float*)d_in[24];
    const float* jk_w   = (const float*)d_in[25];
    const float* jk_b   = (const float*)d_in[26];
    const float* cls_w  = (const float*)d_in[27];
    const float* cls_b  = (const float*)d_in[28];
    float* out = (float*)d_out;

    k_zero<<<49,1024>>>();
    k_hist<<<(EE+1023)/1024,1024>>>(ei);
    k_prep<<<1,32>>>(c1_le, c1_ae, c2_le, c2_ae);
    k_prepcw<<<8,256>>>(cls_w, cls_b, jk_w, jk_b);
    k_scan<<<1,1024>>>();
    k_edge<<<(EE+255)/256,256>>>(ea, ei, ee_w1, ee_b1, ee_w2, ee_b2);
    k_node1<<<(NN+15)/16,128>>>(x, proj_w, proj_b, c1_lin, c1_as, c1_ad);

    // conv1 (fused softmax + aggregate + ELU + residual + LN)
    k_gat<<<(NN+15)/16,512>>>(c1_b, n1_g, n1_b, 0);

    // conv2
    k_node2<<<(NN+127)/128,256>>>(c2_lin);
    k_att2<<<(NN+7)/8,256>>>(c2_as, c2_ad);
    k_gat<<<(NN+15)/16,512>>>(c2_b, n2_g, n2_b, 1);

    // collapsed JK+classifier+log_softmax
    k_out<<<(NN+7)/8,256>>>(out);
}

// round 4
// speedup vs baseline: 2.1327x; 1.0668x over previous
#include <cuda_runtime.h>
#include <math.h>

#define NN 50000
#define EE 800000

// ---------------- scratch (device globals) ----------------
__device__ float g_sae1[EE*4];   // a_edge (conv1) in CSR order
__device__ float g_sae2[EE*4];   // a_edge (conv2) in CSR order
__device__ int   g_ssrc[EE];     // src node in CSR order
__device__ int   g_cnt[NN];
__device__ int   g_cur[NN];
__device__ int   g_rowptr[NN+1];
__device__ float g_h0[NN*128];
__device__ float g_h1[NN*128];
__device__ float g_h2[NN*128];
__device__ float g_xs[NN*128];
__device__ float g_asrc[NN*4];
__device__ float g_adst[NN*4];
__device__ float g_M[32];        // [conv*16 + j*4 + h]
__device__ float g_CW[5*384];    // collapsed classifier: cls_w @ jk_w
__device__ float g_cb2[5];       // collapsed bias

// ---------------- packed f32x2 helpers ----------------
__device__ __forceinline__ unsigned long long pack2(float x){
    unsigned long long r;
    unsigned int u = __float_as_uint(x);
    asm("mov.b64 %0, {%1, %1};" : "=l"(r) : "r"(u));
    return r;
}
__device__ __forceinline__ void fma2(unsigned long long& acc,
                                     unsigned long long a, unsigned long long b){
    asm("fma.rn.f32x2 %0, %1, %2, %0;" : "+l"(acc) : "l"(a), "l"(b));
}

// ---------------- precompute 4x4 edge-attention matrices ----------------
__global__ void k_prep(const float* le1, const float* ae1,
                       const float* le2, const float* ae2){
    int t = threadIdx.x;
    if (t >= 32) return;
    int which = t >> 4, j = (t >> 2) & 3, h = t & 3;
    const float* le = which ? le2 : le1;   // [128,4] row-major
    const float* ae = which ? ae2 : ae1;   // [4,32]  row-major
    float s = 0.f;
    for (int c = 0; c < 32; c++)
        s += le[(h*32+c)*4 + j] * ae[h*32+c];
    g_M[which*16 + j*4 + h] = s;
}

// ---------------- collapsed classifier weights (warp per output) ----------------
__global__ void k_prepcw(const float* __restrict__ cw, const float* __restrict__ cb,
                         const float* __restrict__ jkw, const float* __restrict__ jkb){
    int w = (blockIdx.x*256 + threadIdx.x) >> 5;
    int lane = threadIdx.x & 31;
    if (w >= 5*385) return;
    int c = w / 385, j = w % 385;
    float4 a = *(const float4*)&cw[c*128 + lane*4];
    int d = lane*4;
    float s;
    if (j < 384){
        s = a.x*jkw[(d+0)*384+j] + a.y*jkw[(d+1)*384+j]
          + a.z*jkw[(d+2)*384+j] + a.w*jkw[(d+3)*384+j];
    } else {
        float4 b = *(const float4*)&jkb[d];
        s = a.x*b.x + a.y*b.y + a.z*b.z + a.w*b.w;
    }
    #pragma unroll
    for (int o=16;o>0;o>>=1) s += __shfl_xor_sync(0xffffffffu, s, o);
    if (lane == 0){
        if (j < 384) g_CW[c*384+j] = s;
        else         g_cb2[c] = s + cb[c];
    }
}

// ---------------- CSR build ----------------
__global__ void k_zero(){
    int i = blockIdx.x*1024 + threadIdx.x;
    if (i < NN) g_cnt[i] = 0;
}

__global__ void k_hist(const int* __restrict__ ei){
    int e = blockIdx.x*1024 + threadIdx.x;
    if (e < EE) atomicAdd(&g_cnt[ei[EE+e]], 1);
}

__global__ void k_scan(){
    __shared__ int ssum[1024];
    int t = threadIdx.x;
    int beg = t*49, end = min(beg+49, NN);
    int s = 0;
    for (int i = beg; i < end; i++) s += g_cnt[i];
    ssum[t] = s;
    __syncthreads();
    for (int off = 1; off < 1024; off <<= 1){
        int v = (t >= off) ? ssum[t-off] : 0;
        __syncthreads();
        ssum[t] += v;
        __syncthreads();
    }
    int run = ssum[t] - s;   // exclusive prefix
    for (int i = beg; i < end; i++){
        g_rowptr[i] = run; g_cur[i] = run;
        run += g_cnt[i];
    }
    if (t == 1023) g_rowptr[NN] = ssum[1023];
}

// ---------------- edge encoder + a_edge + CSR scatter (fused) ----------------
__global__ void k_edge(const float* __restrict__ ea, const int* __restrict__ ei,
                       const float* __restrict__ w1, const float* __restrict__ b1,
                       const float* __restrict__ w2, const float* __restrict__ b2){
    __shared__ float sw1[256], sb1[32], sw2[128], sb2[4], sM[32];
    int tid = threadIdx.x;
    if (tid < 256) sw1[tid] = w1[tid];
    if (tid < 32)  sb1[tid] = b1[tid];
    if (tid < 128) sw2[tid] = w2[tid];
    if (tid < 4)   sb2[tid] = b2[tid];
    if (tid >= 32 && tid < 64) sM[tid-32] = g_M[tid-32];
    __syncthreads();
    int e = blockIdx.x*256 + tid;
    if (e >= EE) return;
    float4 v0 = ((const float4*)ea)[e*2];
    float4 v1 = ((const float4*)ea)[e*2+1];
    float av[8] = {v0.x,v0.y,v0.z,v0.w,v1.x,v1.y,v1.z,v1.w};
    float e0=sb2[0], e1=sb2[1], e2=sb2[2], e3=sb2[3];
    #pragma unroll
    for (int c=0;c<32;c++){
        float hv = sb1[c];
        #pragma unroll
        for (int j=0;j<8;j++) hv = fmaf(sw1[c*8+j], av[j], hv);
        hv = fmaxf(hv, 0.f);
        e0 = fmaf(sw2[c],    hv, e0);
        e1 = fmaf(sw2[32+c], hv, e1);
        e2 = fmaf(sw2[64+c], hv, e2);
        e3 = fmaf(sw2[96+c], hv, e3);
    }
    float4 r1, r2;
    r1.x = e0*sM[0] + e1*sM[4] + e2*sM[8]  + e3*sM[12];
    r1.y = e0*sM[1] + e1*sM[5] + e2*sM[9]  + e3*sM[13];
    r1.z = e0*sM[2] + e1*sM[6] + e2*sM[10] + e3*sM[14];
    r1.w = e0*sM[3] + e1*sM[7] + e2*sM[11] + e3*sM[15];
    r2.x = e0*sM[16]+ e1*sM[20]+ e2*sM[24] + e3*sM[28];
    r2.y = e0*sM[17]+ e1*sM[21]+ e2*sM[25] + e3*sM[29];
    r2.z = e0*sM[18]+ e1*sM[22]+ e2*sM[26] + e3*sM[30];
    r2.w = e0*sM[19]+ e1*sM[23]+ e2*sM[27] + e3*sM[31];
    int srcn = ei[e], d = ei[EE+e];
    int pos = atomicAdd(&g_cur[d], 1);
    g_ssrc[pos] = srcn;
    ((float4*)g_sae1)[pos] = r1;
    ((float4*)g_sae2)[pos] = r2;
}

// ---------------- conv1 node transforms: h0, xs1, a_src1, a_dst1 ----------------
__global__ void k_node1(const float* __restrict__ x,
                        const float* __restrict__ pw, const float* __restrict__ pb,
                        const float* __restrict__ lw,
                        const float* __restrict__ asv, const float* __restrict__ adv){
    __shared__ float sWp[16*129], sWl[16*129];
    __shared__ float sx[16*17];
    int tid = threadIdx.x;
    float attS = asv[tid], attD = adv[tid], pbd = pb[tid];
    for (int i=tid;i<2048;i+=128){
        int d=i>>4, k=i&15;
        sWp[k*129+d] = pw[i];
        sWl[k*129+d] = lw[i];
    }
    int n0 = blockIdx.x*16;
    for (int i=tid;i<256;i+=128){
        int n=i>>4, k=i&15;
        int node=n0+n;
        sx[n*17+k] = (node<NN) ? x[node*16+k] : 0.f;
    }
    __syncthreads();
    float acc0[16], acc1[16];
    #pragma unroll
    for (int n=0;n<16;n++){ acc0[n]=pbd; acc1[n]=0.f; }
    #pragma unroll
    for (int k=0;k<16;k++){
        float wp=sWp[k*129+tid], wl=sWl[k*129+tid];
        #pragma unroll
        for (int n=0;n<16;n++){
            float xv = sx[n*17+k];
            acc0[n] = fmaf(xv, wp, acc0[n]);
            acc1[n] = fmaf(xv, wl, acc1[n]);
        }
    }
    int lane = tid&31, h = tid>>5;
    for (int n=0;n<16;n++){
        int node=n0+n;
        if (node>=NN) break;
        g_h0[node*128+tid] = acc0[n];
        g_xs[node*128+tid] = acc1[n];
        float s = acc1[n]*attS, dd = acc1[n]*attD;
        #pragma unroll
        for (int o=16;o>0;o>>=1){
            s  += __shfl_down_sync(0xffffffffu, s, o);
            dd += __shfl_down_sync(0xffffffffu, dd, o);
        }
        if (lane==0){ g_asrc[node*4+h]=s; g_adst[node*4+h]=dd; }
    }
}

// ---------------- fused GAT conv: softmax + aggregate + ELU + residual + LN ----------------
__global__ void __launch_bounds__(512) k_gat(const float* __restrict__ bias,
                      const float* __restrict__ gam,
                      const float* __restrict__ bet, int conv){
    __shared__ float sw[16][128];
    __shared__ int   ss[16][32];
    int wid = threadIdx.x >> 5, lane = threadIdx.x & 31;
    int node = blockIdx.x*16 + wid;
    if (node >= NN) return;
    int h = lane >> 3;
    const float4* __restrict__ sae   = (const float4*)(conv ? g_sae2 : g_sae1);
    const float4* __restrict__ asrc4 = (const float4*)g_asrc;
    const float4* __restrict__ xs4   = (const float4*)g_xs;
    float4 ad = ((const float4*)g_adst)[node];
    int beg = g_rowptr[node], end = g_rowptr[node+1];
    float4 den = make_float4(0.f,0.f,0.f,0.f);
    float4 acc = make_float4(0.f,0.f,0.f,0.f);
    for (int base = beg; base < end; base += 32){
        int idx = base + lane;
        bool v = idx < end;
        int s = g_ssrc[v ? idx : end-1];
        float4 w = make_float4(0.f,0.f,0.f,0.f);
        if (v){
            float4 ae = sae[idx];
            float4 as = asrc4[s];
            float ax = as.x+ad.x+ae.x; ax = ax>0.f?ax:0.2f*ax;
            float ay = as.y+ad.y+ae.y; ay = ay>0.f?ay:0.2f*ay;
            float az = as.z+ad.z+ae.z; az = az>0.f?az:0.2f*az;
            float aw = as.w+ad.w+ae.w; aw = aw>0.f?aw:0.2f*aw;
            w = make_float4(__expf(ax), __expf(ay), __expf(az), __expf(aw));
        }
        den.x += w.x; den.y += w.y; den.z += w.z; den.w += w.w;
        __syncwarp();
        ss[wid][lane] = s;
        ((float4*)sw[wid])[lane] = w;
        __syncwarp();
        int cnt = end - base; if (cnt > 32) cnt = 32;
        // chunks of 8, skip fully-dead chunks (avg degree 16 << 32)
        for (int c = 0; c < cnt; c += 8){
            #pragma unroll
            for (int j = 0; j < 8; j++){
                int   sj = ss[wid][c+j];
                float wj = sw[wid][(c+j)*4 + h];
                float4 xv = xs4[sj*32 + lane];
                acc.x = fmaf(wj, xv.x, acc.x);
                acc.y = fmaf(wj, xv.y, acc.y);
                acc.z = fmaf(wj, xv.z, acc.z);
                acc.w = fmaf(wj, xv.w, acc.w);
            }
        }
    }
    // reduce denominator across warp (per head)
    #pragma unroll
    for (int o=16;o>0;o>>=1){
        den.x += __shfl_xor_sync(0xffffffffu, den.x, o);
        den.y += __shfl_xor_sync(0xffffffffu, den.y, o);
        den.z += __shfl_xor_sync(0xffffffffu, den.z, o);
        den.w += __shfl_xor_sync(0xffffffffu, den.w, o);
    }
    float dh = (h==0)?den.x:(h==1)?den.y:(h==2)?den.z:den.w;
    float inv = 1.f/(dh + 1e-16f);
    // epilogue: bias + ELU + residual + layernorm
    const float* hp = conv ? g_h1 : g_h0;
    float*       ho = conv ? g_h2 : g_h1;
    float4 hv = ((const float4*)hp)[node*32+lane];
    float4 bv = *(const float4*)&bias[lane*4];
    float4 r;
    r.x = acc.x*inv + bv.x; r.x = (r.x>0.f)?r.x:(__expf(r.x)-1.f); r.x += hv.x;
    r.y = acc.y*inv + bv.y; r.y = (r.y>0.f)?r.y:(__expf(r.y)-1.f); r.y += hv.y;
    r.z = acc.z*inv + bv.z; r.z = (r.z>0.f)?r.z:(__expf(r.z)-1.f); r.z += hv.z;
    r.w = acc.w*inv + bv.w; r.w = (r.w>0.f)?r.w:(__expf(r.w)-1.f); r.w += hv.w;
    float s1 = r.x+r.y+r.z+r.w;
    float s2 = r.x*r.x + r.y*r.y + r.z*r.z + r.w*r.w;
    #pragma unroll
    for (int o=16;o>0;o>>=1){
        s1 += __shfl_xor_sync(0xffffffffu, s1, o);
        s2 += __shfl_xor_sync(0xffffffffu, s2, o);
    }
    float mu  = s1 * (1.f/128.f);
    float var = s2 * (1.f/128.f) - mu*mu;
    float rs  = rsqrtf(var + 1e-5f);
    float4 gv = *(const float4*)&gam[lane*4];
    float4 be = *(const float4*)&bet[lane*4];
    float4 o4;
    o4.x = (r.x-mu)*rs*gv.x + be.x;
    o4.y = (r.y-mu)*rs*gv.y + be.y;
    o4.z = (r.z-mu)*rs*gv.z + be.z;
    o4.w = (r.w-mu)*rs*gv.w + be.w;
    ((float4*)ho)[node*32+lane] = o4;
}

// ---------------- conv2 GEMM: xs = h1 @ c2_lin^T via packed f32x2 FMA ----------------
__global__ void __launch_bounds__(256) k_node2(const float* __restrict__ lin){
    __shared__ float sA[16*132];
    __shared__ float sB[16*132];
    int tid = threadIdx.x;
    int tx = tid & 15, ty = tid >> 4;
    int n0 = blockIdx.x*128;
    unsigned long long acc[8][4];
    #pragma unroll
    for (int r=0;r<8;r++)
        #pragma unroll
        for (int p=0;p<4;p++) acc[r][p] = 0ULL;
    for (int kc=0;kc<8;kc++){
        __syncthreads();
        #pragma unroll
        for (int t=tid;t<512;t+=256){
            int r = t>>2, q = t&3;
            int node = n0 + r;
            float4 v = (node<NN) ? *(const float4*)&g_h1[node*128 + kc*16 + q*4]
                                 : make_float4(0.f,0.f,0.f,0.f);
            sA[(q*4+0)*132+r]=v.x; sA[(q*4+1)*132+r]=v.y;
            sA[(q*4+2)*132+r]=v.z; sA[(q*4+3)*132+r]=v.w;
        }
        #pragma unroll
        for (int t=tid;t<512;t+=256){
            int d = t>>2, q = t&3;
            float4 v = *(const float4*)&lin[d*128 + kc*16 + q*4];
            sB[(q*4+0)*132+d]=v.x; sB[(q*4+1)*132+d]=v.y;
            sB[(q*4+2)*132+d]=v.z; sB[(q*4+3)*132+d]=v.w;
        }
        __syncthreads();
        #pragma unroll
        for (int k=0;k<16;k++){
            float4 a0 = *(const float4*)&sA[k*132 + ty*8];
            float4 a1 = *(const float4*)&sA[k*132 + ty*8 + 4];
            ulonglong2 b0 = *(const ulonglong2*)&sB[k*132 + tx*8];
            ulonglong2 b1 = *(const ulonglong2*)&sB[k*132 + tx*8 + 4];
            unsigned long long bp0=b0.x, bp1=b0.y, bp2=b1.x, bp3=b1.y;
            float ar[8] = {a0.x,a0.y,a0.z,a0.w,a1.x,a1.y,a1.z,a1.w};
            #pragma unroll
            for (int r=0;r<8;r++){
                unsigned long long a2 = pack2(ar[r]);
                fma2(acc[r][0], a2, bp0);
                fma2(acc[r][1], a2, bp1);
                fma2(acc[r][2], a2, bp2);
                fma2(acc[r][3], a2, bp3);
            }
        }
    }
    #pragma unroll
    for (int r=0;r<8;r++){
        int node = n0 + ty*8 + r;
        if (node < NN){
            ulonglong2 v0; v0.x = acc[r][0]; v0.y = acc[r][1];
            ulonglong2 v1; v1.x = acc[r][2]; v1.y = acc[r][3];
            *(ulonglong2*)&g_xs[node*128 + tx*8]     = v0;
            *(ulonglong2*)&g_xs[node*128 + tx*8 + 4] = v1;
        }
    }
}

// ---------------- conv2 attention dots ----------------
__global__ void k_att2(const float* __restrict__ asv, const float* __restrict__ adv){
    int node = blockIdx.x*8 + (threadIdx.x>>5);
    if (node >= NN) return;
    int lane = threadIdx.x & 31;
    int h = lane >> 3;
    float4 xv = ((const float4*)g_xs)[node*32+lane];
    float4 ws = *(const float4*)&asv[lane*4];
    float4 wd = *(const float4*)&adv[lane*4];
    float s = xv.x*ws.x + xv.y*ws.y + xv.z*ws.z + xv.w*ws.w;
    float d = xv.x*wd.x + xv.y*wd.y + xv.z*wd.z + xv.w*wd.w;
    #pragma unroll
    for (int o=1;o<8;o<<=1){
        s += __shfl_xor_sync(0xffffffffu, s, o);
        d += __shfl_xor_sync(0xffffffffu, d, o);
    }
    if ((lane&7)==0){ g_asrc[node*4+h]=s; g_adst[node*4+h]=d; }
}

// ---------------- collapsed output: logits + log_softmax ----------------
__global__ void k_out(float* __restrict__ out){
    __shared__ float sCW[5*384];
    __shared__ float sCB[5];
    int tid = threadIdx.x;
    for (int i=tid;i<1920;i+=256) sCW[i] = g_CW[i];
    if (tid < 5) sCB[tid] = g_cb2[tid];
    __syncthreads();
    int node = blockIdx.x*8 + (tid>>5);
    if (node >= NN) return;
    int lane = tid & 31;
    float4 a0 = ((const float4*)g_h0)[node*32+lane];
    float4 a1 = ((const float4*)g_h1)[node*32+lane];
    float4 a2 = ((const float4*)g_h2)[node*32+lane];
    float lg[5];
    #pragma unroll
    for (int c=0;c<5;c++){
        const float* w = &sCW[c*384];
        float4 b0 = *(const float4*)&w[lane*4];
        float4 b1 = *(const float4*)&w[128 + lane*4];
        float4 b2 = *(const float4*)&w[256 + lane*4];
        float p = a0.x*b0.x + a0.y*b0.y + a0.z*b0.z + a0.w*b0.w;
        p = fmaf(a1.x,b1.x, fmaf(a1.y,b1.y, fmaf(a1.z,b1.z, fmaf(a1.w,b1.w, p))));
        p = fmaf(a2.x,b2.x, fmaf(a2.y,b2.y, fmaf(a2.z,b2.z, fmaf(a2.w,b2.w, p))));
        #pragma unroll
        for (int o=16;o>0;o>>=1) p += __shfl_xor_sync(0xffffffffu, p, o);
        lg[c] = p + sCB[c];
    }
    if (lane == 0){
        float m = lg[0];
        #pragma unroll
        for (int c=1;c<5;c++) m = fmaxf(m, lg[c]);
        float s = 0.f;
        #pragma unroll
        for (int c=0;c<5;c++) s += __expf(lg[c]-m);
        float ls = logf(s);
        #pragma unroll
        for (int c=0;c<5;c++) out[node*5+c] = lg[c]-m-ls;
    }
}

// ---------------- launcher ----------------
extern "C" void kernel_launch(void* const* d_in, const int* in_sizes, int n_in,
                              void* d_out, int out_size){
    const float* x      = (const float*)d_in[0];
    const int*   ei     = (const int*)  d_in[1];
    const float* ea     = (const float*)d_in[2];
    const float* ee_w1  = (const float*)d_in[3];
    const float* ee_b1  = (const float*)d_in[4];
    const float* ee_w2  = (const float*)d_in[5];
    const float* ee_b2  = (const float*)d_in[6];
    const float* proj_w = (const float*)d_in[7];
    const float* proj_b = (const float*)d_in[8];
    const float* c1_lin = (const float*)d_in[9];
    const float* c1_as  = (const float*)d_in[10];
    const float* c1_ad  = (const float*)d_in[11];
    const float* c1_le  = (const float*)d_in[12];
    const float* c1_ae  = (const float*)d_in[13];
    const float* c1_b   = (const float*)d_in[14];
    const float* c2_lin = (const float*)d_in[15];
    const float* c2_as  = (const float*)d_in[16];
    const float* c2_ad  = (const float*)d_in[17];
    const float* c2_le  = (const float*)d_in[18];
    const float* c2_ae  = (const float*)d_in[19];
    const float* c2_b   = (const float*)d_in[20];
    const float* n1_g   = (const float*)d_in[21];
    const float* n1_b   = (const float*)d_in[22];
    const float* n2_g   = (const float*)d_in[23];
    const float* n2_b   = (const float*)d_in[24];
    const float* jk_w   = (const float*)d_in[25];
    const float* jk_b   = (const float*)d_in[26];
    const float* cls_w  = (const float*)d_in[27];
    const float* cls_b  = (const float*)d_in[28];
    float* out = (float*)d_out;

    k_zero<<<49,1024>>>();
    k_hist<<<(EE+1023)/1024,1024>>>(ei);
    k_prep<<<1,32>>>(c1_le, c1_ae, c2_le, c2_ae);
    k_prepcw<<<(5*385*32+255)/256,256>>>(cls_w, cls_b, jk_w, jk_b);
    k_scan<<<1,1024>>>();
    k_edge<<<(EE+255)/256,256>>>(ea, ei, ee_w1, ee_b1, ee_w2, ee_b2);
    k_node1<<<(NN+15)/16,128>>>(x, proj_w, proj_b, c1_lin, c1_as, c1_ad);

    // conv1 (fused softmax + aggregate + ELU + residual + LN)
    k_gat<<<(NN+15)/16,512>>>(c1_b, n1_g, n1_b, 0);

    // conv2
    k_node2<<<(NN+127)/128,256>>>(c2_lin);
    k_att2<<<(NN+7)/8,256>>>(c2_as, c2_ad);
    k_gat<<<(NN+15)/16,512>>>(c2_b, n2_g, n2_b, 1);

    // collapsed JK+classifier+log_softmax
    k_out<<<(NN+7)/8,256>>>(out);
}

// round 5
// speedup vs baseline: 2.3630x; 1.1080x over previous
#include <cuda_runtime.h>
#include <math.h>

#define NN 50000
#define EE 800000

// ---------------- scratch (device globals) ----------------
__device__ float g_sae1[EE*4];   // a_edge (conv1) in CSR order
__device__ float g_sae2[EE*4];   // a_edge (conv2) in CSR order
__device__ int   g_ssrc[EE];     // src node in CSR order
__device__ int   g_cnt[NN];
__device__ int   g_cur[NN];
__device__ int   g_rowptr[NN+1];
__device__ float g_h0[NN*128];
__device__ float g_h1[NN*128];
__device__ float g_h2[NN*128];
__device__ float g_xs[NN*128];
__device__ float g_asrc[NN*4];
__device__ float g_adst[NN*4];
__device__ float g_M[32];        // [conv*16 + j*4 + h]
__device__ float g_CW[5*384];    // collapsed classifier: cls_w @ jk_w
__device__ float g_cb2[5];       // collapsed bias

// ---------------- packed f32x2 helpers ----------------
__device__ __forceinline__ unsigned long long pack2(float x){
    unsigned long long r;
    unsigned int u = __float_as_uint(x);
    asm("mov.b64 %0, {%1, %1};" : "=l"(r) : "r"(u));
    return r;
}
__device__ __forceinline__ void fma2(unsigned long long& acc,
                                     unsigned long long a, unsigned long long b){
    asm("fma.rn.f32x2 %0, %1, %2, %0;" : "+l"(acc) : "l"(a), "l"(b));
}
__device__ __forceinline__ float lo2(unsigned long long v){
    unsigned int a, b;
    asm("mov.b64 {%0, %1}, %2;" : "=r"(a), "=r"(b) : "l"(v));
    return __uint_as_float(a);
}
__device__ __forceinline__ float hi2(unsigned long long v){
    unsigned int a, b;
    asm("mov.b64 {%0, %1}, %2;" : "=r"(a), "=r"(b) : "l"(v));
    return __uint_as_float(b);
}

// ---------------- fused init: zero g_cnt + prep M + collapsed classifier ----------------
__global__ void k_init(const float* __restrict__ le1, const float* __restrict__ ae1,
                       const float* __restrict__ le2, const float* __restrict__ ae2,
                       const float* __restrict__ cw,  const float* __restrict__ cb,
                       const float* __restrict__ jkw, const float* __restrict__ jkb){
    int b = blockIdx.x;
    if (b < 49){
        int t = b*256 + threadIdx.x;
        if (t < NN/4){
            int4 z; z.x=0; z.y=0; z.z=0; z.w=0;
            ((int4*)g_cnt)[t] = z;
        }
    } else if (b == 49){
        int t = threadIdx.x;
        if (t < 32){
            int which = t >> 4, j = (t >> 2) & 3, h = t & 3;
            const float* le = which ? le2 : le1;
            const float* ae = which ? ae2 : ae1;
            float s = 0.f;
            for (int c = 0; c < 32; c++)
                s += le[(h*32+c)*4 + j] * ae[h*32+c];
            g_M[which*16 + j*4 + h] = s;
        }
    } else {
        int w = (b-50)*8 + (threadIdx.x >> 5);
        int lane = threadIdx.x & 31;
        if (w >= 5*385) return;
        int c = w / 385, j = w % 385;
        float4 a = *(const float4*)&cw[c*128 + lane*4];
        int d = lane*4;
        float s;
        if (j < 384){
            s = a.x*jkw[(d+0)*384+j] + a.y*jkw[(d+1)*384+j]
              + a.z*jkw[(d+2)*384+j] + a.w*jkw[(d+3)*384+j];
        } else {
            float4 bb = *(const float4*)&jkb[d];
            s = a.x*bb.x + a.y*bb.y + a.z*bb.z + a.w*bb.w;
        }
        #pragma unroll
        for (int o=16;o>0;o>>=1) s += __shfl_xor_sync(0xffffffffu, s, o);
        if (lane == 0){
            if (j < 384) g_CW[c*384+j] = s;
            else         g_cb2[c] = s + cb[c];
        }
    }
}

// ---------------- histogram (int4 vectorized) ----------------
__global__ void k_hist(const int* __restrict__ ei){
    int t = blockIdx.x*256 + threadIdx.x;
    if (t < EE/4){
        int4 d4 = ((const int4*)(ei+EE))[t];
        atomicAdd(&g_cnt[d4.x], 1);
        atomicAdd(&g_cnt[d4.y], 1);
        atomicAdd(&g_cnt[d4.z], 1);
        atomicAdd(&g_cnt[d4.w], 1);
    }
}

// ---------------- scan ----------------
__global__ void k_scan(){
    __shared__ int ssum[1024];
    int t = threadIdx.x;
    int beg = t*49, end = min(beg+49, NN);
    int s = 0;
    for (int i = beg; i < end; i++) s += g_cnt[i];
    ssum[t] = s;
    __syncthreads();
    for (int off = 1; off < 1024; off <<= 1){
        int v = (t >= off) ? ssum[t-off] : 0;
        __syncthreads();
        ssum[t] += v;
        __syncthreads();
    }
    int run = ssum[t] - s;   // exclusive prefix
    for (int i = beg; i < end; i++){
        g_rowptr[i] = run; g_cur[i] = run;
        run += g_cnt[i];
    }
    if (t == 1023) g_rowptr[NN] = ssum[1023];
}

// ---------------- edge encoder + a_edge + CSR scatter (vectorized smem) ----------------
__global__ void k_edge(const float* __restrict__ ea, const int* __restrict__ ei,
                       const float* __restrict__ w1, const float* __restrict__ b1,
                       const float* __restrict__ w2, const float* __restrict__ b2){
    __shared__ __align__(16) float sw1[256];
    __shared__ float sb1[32];
    __shared__ __align__(16) float sw2t[128];   // [c][h]
    __shared__ float sb2v[4], sM[32];
    int tid = threadIdx.x;
    if (tid < 256) sw1[tid] = w1[tid];
    if (tid < 32)  sb1[tid] = b1[tid];
    if (tid < 128){ int h = tid>>5, c = tid&31; sw2t[c*4+h] = w2[tid]; }
    if (tid < 4)   sb2v[tid] = b2[tid];
    if (tid >= 64 && tid < 96) sM[tid-64] = g_M[tid-64];
    __syncthreads();
    int e = blockIdx.x*256 + tid;
    if (e >= EE) return;
    float4 v0 = ((const float4*)ea)[e*2];
    float4 v1 = ((const float4*)ea)[e*2+1];
    float e0=sb2v[0], e1=sb2v[1], e2=sb2v[2], e3=sb2v[3];
    #pragma unroll
    for (int c=0;c<32;c++){
        float4 wa = *(const float4*)&sw1[c*8];
        float4 wb = *(const float4*)&sw1[c*8+4];
        float hv = sb1[c];
        hv = fmaf(wa.x, v0.x, hv); hv = fmaf(wa.y, v0.y, hv);
        hv = fmaf(wa.z, v0.z, hv); hv = fmaf(wa.w, v0.w, hv);
        hv = fmaf(wb.x, v1.x, hv); hv = fmaf(wb.y, v1.y, hv);
        hv = fmaf(wb.z, v1.z, hv); hv = fmaf(wb.w, v1.w, hv);
        hv = fmaxf(hv, 0.f);
        float4 w2v = *(const float4*)&sw2t[c*4];
        e0 = fmaf(w2v.x, hv, e0);
        e1 = fmaf(w2v.y, hv, e1);
        e2 = fmaf(w2v.z, hv, e2);
        e3 = fmaf(w2v.w, hv, e3);
    }
    float4 r1, r2;
    r1.x = e0*sM[0] + e1*sM[4] + e2*sM[8]  + e3*sM[12];
    r1.y = e0*sM[1] + e1*sM[5] + e2*sM[9]  + e3*sM[13];
    r1.z = e0*sM[2] + e1*sM[6] + e2*sM[10] + e3*sM[14];
    r1.w = e0*sM[3] + e1*sM[7] + e2*sM[11] + e3*sM[15];
    r2.x = e0*sM[16]+ e1*sM[20]+ e2*sM[24] + e3*sM[28];
    r2.y = e0*sM[17]+ e1*sM[21]+ e2*sM[25] + e3*sM[29];
    r2.z = e0*sM[18]+ e1*sM[22]+ e2*sM[26] + e3*sM[30];
    r2.w = e0*sM[19]+ e1*sM[23]+ e2*sM[27] + e3*sM[31];
    int srcn = ei[e], d = ei[EE+e];
    int pos = atomicAdd(&g_cur[d], 1);
    g_ssrc[pos] = srcn;
    ((float4*)g_sae1)[pos] = r1;
    ((float4*)g_sae2)[pos] = r2;
}

// ---------------- conv1 node transforms: weights in registers ----------------
__global__ void k_node1(const float* __restrict__ x,
                        const float* __restrict__ pw, const float* __restrict__ pb,
                        const float* __restrict__ lw,
                        const float* __restrict__ asv, const float* __restrict__ adv){
    __shared__ __align__(16) float sx[16*20];
    int tid = threadIdx.x;  // = output dim d
    float attS = asv[tid], attD = adv[tid], pbd = pb[tid];
    float wp[16], wl[16];
    #pragma unroll
    for (int q=0;q<4;q++){
        float4 a = *(const float4*)&pw[tid*16 + q*4];
        wp[q*4+0]=a.x; wp[q*4+1]=a.y; wp[q*4+2]=a.z; wp[q*4+3]=a.w;
        float4 b = *(const float4*)&lw[tid*16 + q*4];
        wl[q*4+0]=b.x; wl[q*4+1]=b.y; wl[q*4+2]=b.z; wl[q*4+3]=b.w;
    }
    int n0 = blockIdx.x*16;
    for (int i=tid;i<256;i+=128){
        int n=i>>4, k=i&15;
        int node=n0+n;
        sx[n*20+k] = (node<NN) ? x[node*16+k] : 0.f;
    }
    __syncthreads();
    float acc0[16], acc1[16];
    #pragma unroll
    for (int n=0;n<16;n++){ acc0[n]=pbd; acc1[n]=0.f; }
    #pragma unroll
    for (int n=0;n<16;n++){
        float4 x0 = *(const float4*)&sx[n*20];
        float4 x1 = *(const float4*)&sx[n*20+4];
        float4 x2 = *(const float4*)&sx[n*20+8];
        float4 x3 = *(const float4*)&sx[n*20+12];
        float xv[16] = {x0.x,x0.y,x0.z,x0.w, x1.x,x1.y,x1.z,x1.w,
                        x2.x,x2.y,x2.z,x2.w, x3.x,x3.y,x3.z,x3.w};
        #pragma unroll
        for (int k=0;k<16;k++){
            acc0[n] = fmaf(xv[k], wp[k], acc0[n]);
            acc1[n] = fmaf(xv[k], wl[k], acc1[n]);
        }
    }
    int lane = tid&31, h = tid>>5;
    for (int n=0;n<16;n++){
        int node=n0+n;
        if (node>=NN) break;
        g_h0[node*128+tid] = acc0[n];
        g_xs[node*128+tid] = acc1[n];
        float s = acc1[n]*attS, dd = acc1[n]*attD;
        #pragma unroll
        for (int o=16;o>0;o>>=1){
            s  += __shfl_down_sync(0xffffffffu, s, o);
            dd += __shfl_down_sync(0xffffffffu, dd, o);
        }
        if (lane==0){ g_asrc[node*4+h]=s; g_adst[node*4+h]=dd; }
    }
}

// ---------------- fused GAT conv: softmax + aggregate + ELU + residual + LN ----------------
__global__ void __launch_bounds__(512) k_gat(const float* __restrict__ bias,
                      const float* __restrict__ gam,
                      const float* __restrict__ bet, int conv){
    __shared__ float sw[16][128];
    __shared__ int   ss[16][32];
    int wid = threadIdx.x >> 5, lane = threadIdx.x & 31;
    int node = blockIdx.x*16 + wid;
    if (node >= NN) return;
    int h = lane >> 3;
    const float4* __restrict__ sae   = (const float4*)(conv ? g_sae2 : g_sae1);
    const float4* __restrict__ asrc4 = (const float4*)g_asrc;
    const float4* __restrict__ xs4   = (const float4*)g_xs;
    float4 ad = ((const float4*)g_adst)[node];
    int beg = g_rowptr[node], end = g_rowptr[node+1];
    float4 den = make_float4(0.f,0.f,0.f,0.f);
    float4 acc = make_float4(0.f,0.f,0.f,0.f);
    for (int base = beg; base < end; base += 32){
        int idx = base + lane;
        bool v = idx < end;
        int s = g_ssrc[v ? idx : end-1];
        float4 w = make_float4(0.f,0.f,0.f,0.f);
        if (v){
            float4 ae = sae[idx];
            float4 as = asrc4[s];
            float ax = as.x+ad.x+ae.x; ax = ax>0.f?ax:0.2f*ax;
            float ay = as.y+ad.y+ae.y; ay = ay>0.f?ay:0.2f*ay;
            float az = as.z+ad.z+ae.z; az = az>0.f?az:0.2f*az;
            float aw = as.w+ad.w+ae.w; aw = aw>0.f?aw:0.2f*aw;
            w = make_float4(__expf(ax), __expf(ay), __expf(az), __expf(aw));
        }
        den.x += w.x; den.y += w.y; den.z += w.z; den.w += w.w;
        __syncwarp();
        ss[wid][lane] = s;
        ((float4*)sw[wid])[lane] = w;
        __syncwarp();
        int cnt = end - base; if (cnt > 32) cnt = 32;
        for (int c = 0; c < cnt; c += 8){
            #pragma unroll
            for (int j = 0; j < 8; j++){
                int   sj = ss[wid][c+j];
                float wj = sw[wid][(c+j)*4 + h];
                float4 xv = xs4[sj*32 + lane];
                acc.x = fmaf(wj, xv.x, acc.x);
                acc.y = fmaf(wj, xv.y, acc.y);
                acc.z = fmaf(wj, xv.z, acc.z);
                acc.w = fmaf(wj, xv.w, acc.w);
            }
        }
    }
    #pragma unroll
    for (int o=16;o>0;o>>=1){
        den.x += __shfl_xor_sync(0xffffffffu, den.x, o);
        den.y += __shfl_xor_sync(0xffffffffu, den.y, o);
        den.z += __shfl_xor_sync(0xffffffffu, den.z, o);
        den.w += __shfl_xor_sync(0xffffffffu, den.w, o);
    }
    float dh = (h==0)?den.x:(h==1)?den.y:(h==2)?den.z:den.w;
    float inv = 1.f/(dh + 1e-16f);
    const float* hp = conv ? g_h1 : g_h0;
    float*       ho = conv ? g_h2 : g_h1;
    float4 hv = ((const float4*)hp)[node*32+lane];
    float4 bv = *(const float4*)&bias[lane*4];
    float4 r;
    r.x = acc.x*inv + bv.x; r.x = (r.x>0.f)?r.x:(__expf(r.x)-1.f); r.x += hv.x;
    r.y = acc.y*inv + bv.y; r.y = (r.y>0.f)?r.y:(__expf(r.y)-1.f); r.y += hv.y;
    r.z = acc.z*inv + bv.z; r.z = (r.z>0.f)?r.z:(__expf(r.z)-1.f); r.z += hv.z;
    r.w = acc.w*inv + bv.w; r.w = (r.w>0.f)?r.w:(__expf(r.w)-1.f); r.w += hv.w;
    float s1 = r.x+r.y+r.z+r.w;
    float s2 = r.x*r.x + r.y*r.y + r.z*r.z + r.w*r.w;
    #pragma unroll
    for (int o=16;o>0;o>>=1){
        s1 += __shfl_xor_sync(0xffffffffu, s1, o);
        s2 += __shfl_xor_sync(0xffffffffu, s2, o);
    }
    float mu  = s1 * (1.f/128.f);
    float var = s2 * (1.f/128.f) - mu*mu;
    float rs  = rsqrtf(var + 1e-5f);
    float4 gv = *(const float4*)&gam[lane*4];
    float4 be = *(const float4*)&bet[lane*4];
    float4 o4;
    o4.x = (r.x-mu)*rs*gv.x + be.x;
    o4.y = (r.y-mu)*rs*gv.y + be.y;
    o4.z = (r.z-mu)*rs*gv.z + be.z;
    o4.w = (r.w-mu)*rs*gv.w + be.w;
    ((float4*)ho)[node*32+lane] = o4;
}

// ---------------- conv2 GEMM + fused attention dots ----------------
__global__ void __launch_bounds__(256) k_node2(const float* __restrict__ lin,
                                               const float* __restrict__ asv,
                                               const float* __restrict__ adv){
    __shared__ float sA[16*132];
    __shared__ float sB[16*132];
    int tid = threadIdx.x;
    int tx = tid & 15, ty = tid >> 4;
    int n0 = blockIdx.x*128;
    unsigned long long acc[8][4];
    #pragma unroll
    for (int r=0;r<8;r++)
        #pragma unroll
        for (int p=0;p<4;p++) acc[r][p] = 0ULL;
    for (int kc=0;kc<8;kc++){
        __syncthreads();
        #pragma unroll
        for (int t=tid;t<512;t+=256){
            int r = t>>2, q = t&3;
            int node = n0 + r;
            float4 v = (node<NN) ? *(const float4*)&g_h1[node*128 + kc*16 + q*4]
                                 : make_float4(0.f,0.f,0.f,0.f);
            sA[(q*4+0)*132+r]=v.x; sA[(q*4+1)*132+r]=v.y;
            sA[(q*4+2)*132+r]=v.z; sA[(q*4+3)*132+r]=v.w;
        }
        #pragma unroll
        for (int t=tid;t<512;t+=256){
            int d = t>>2, q = t&3;
            float4 v = *(const float4*)&lin[d*128 + kc*16 + q*4];
            sB[(q*4+0)*132+d]=v.x; sB[(q*4+1)*132+d]=v.y;
            sB[(q*4+2)*132+d]=v.z; sB[(q*4+3)*132+d]=v.w;
        }
        __syncthreads();
        #pragma unroll
        for (int k=0;k<16;k++){
            float4 a0 = *(const float4*)&sA[k*132 + ty*8];
            float4 a1 = *(const float4*)&sA[k*132 + ty*8 + 4];
            ulonglong2 b0 = *(const ulonglong2*)&sB[k*132 + tx*8];
            ulonglong2 b1 = *(const ulonglong2*)&sB[k*132 + tx*8 + 4];
            unsigned long long bp0=b0.x, bp1=b0.y, bp2=b1.x, bp3=b1.y;
            float ar[8] = {a0.x,a0.y,a0.z,a0.w,a1.x,a1.y,a1.z,a1.w};
            #pragma unroll
            for (int r=0;r<8;r++){
                unsigned long long a2 = pack2(ar[r]);
                fma2(acc[r][0], a2, bp0);
                fma2(acc[r][1], a2, bp1);
                fma2(acc[r][2], a2, bp2);
                fma2(acc[r][3], a2, bp3);
            }
        }
    }
    // attention weight slices for this thread's 8 dims
    float4 ws0 = *(const float4*)&asv[tx*8];
    float4 ws1 = *(const float4*)&asv[tx*8+4];
    float4 wd0 = *(const float4*)&adv[tx*8];
    float4 wd1 = *(const float4*)&adv[tx*8+4];
    int hh = tx >> 2;   // head of this thread's 8 dims (32 dims/head = 4 threads)
    #pragma unroll
    for (int r=0;r<8;r++){
        int node = n0 + ty*8 + r;
        if (node < NN){
            float f0=lo2(acc[r][0]), f1=hi2(acc[r][0]);
            float f2=lo2(acc[r][1]), f3=hi2(acc[r][1]);
            float f4=lo2(acc[r][2]), f5=hi2(acc[r][2]);
            float f6=lo2(acc[r][3]), f7=hi2(acc[r][3]);
            ulonglong2 v0; v0.x = acc[r][0]; v0.y = acc[r][1];
            ulonglong2 v1; v1.x = acc[r][2]; v1.y = acc[r][3];
            *(ulonglong2*)&g_xs[node*128 + tx*8]     = v0;
            *(ulonglong2*)&g_xs[node*128 + tx*8 + 4] = v1;
            float s = f0*ws0.x + f1*ws0.y + f2*ws0.z + f3*ws0.w
                    + f4*ws1.x + f5*ws1.y + f6*ws1.z + f7*ws1.w;
            float d = f0*wd0.x + f1*wd0.y + f2*wd0.z + f3*wd0.w
                    + f4*wd1.x + f5*wd1.y + f6*wd1.z + f7*wd1.w;
            s += __shfl_xor_sync(0xffffffffu, s, 1);
            s += __shfl_xor_sync(0xffffffffu, s, 2);
            d += __shfl_xor_sync(0xffffffffu, d, 1);
            d += __shfl_xor_sync(0xffffffffu, d, 2);
            if ((tx & 3) == 0){
                g_asrc[node*4+hh] = s;
                g_adst[node*4+hh] = d;
            }
        }
    }
}

// ---------------- collapsed output: logits + log_softmax ----------------
__global__ void k_out(float* __restrict__ out){
    __shared__ float sCW[5*384];
    __shared__ float sCB[5];
    int tid = threadIdx.x;
    for (int i=tid;i<1920;i+=256) sCW[i] = g_CW[i];
    if (tid < 5) sCB[tid] = g_cb2[tid];
    __syncthreads();
    int node = blockIdx.x*8 + (tid>>5);
    if (node >= NN) return;
    int lane = tid & 31;
    float4 a0 = ((const float4*)g_h0)[node*32+lane];
    float4 a1 = ((const float4*)g_h1)[node*32+lane];
    float4 a2 = ((const float4*)g_h2)[node*32+lane];
    float lg[5];
    #pragma unroll
    for (int c=0;c<5;c++){
        const float* w = &sCW[c*384];
        float4 b0 = *(const float4*)&w[lane*4];
        float4 b1 = *(const float4*)&w[128 + lane*4];
        float4 b2 = *(const float4*)&w[256 + lane*4];
        float p = a0.x*b0.x + a0.y*b0.y + a0.z*b0.z + a0.w*b0.w;
        p = fmaf(a1.x,b1.x, fmaf(a1.y,b1.y, fmaf(a1.z,b1.z, fmaf(a1.w,b1.w, p))));
        p = fmaf(a2.x,b2.x, fmaf(a2.y,b2.y, fmaf(a2.z,b2.z, fmaf(a2.w,b2.w, p))));
        #pragma unroll
        for (int o=16;o>0;o>>=1) p += __shfl_xor_sync(0xffffffffu, p, o);
        lg[c] = p + sCB[c];
    }
    if (lane == 0){
        float m = lg[0];
        #pragma unroll
        for (int c=1;c<5;c++) m = fmaxf(m, lg[c]);
        float s = 0.f;
        #pragma unroll
        for (int c=0;c<5;c++) s += __expf(lg[c]-m);
        float ls = logf(s);
        #pragma unroll
        for (int c=0;c<5;c++) out[node*5+c] = lg[c]-m-ls;
    }
}

// ---------------- launcher ----------------
extern "C" void kernel_launch(void* const* d_in, const int* in_sizes, int n_in,
                              void* d_out, int out_size){
    const float* x      = (const float*)d_in[0];
    const int*   ei     = (const int*)  d_in[1];
    const float* ea     = (const float*)d_in[2];
    const float* ee_w1  = (const float*)d_in[3];
    const float* ee_b1  = (const float*)d_in[4];
    const float* ee_w2  = (const float*)d_in[5];
    const float* ee_b2  = (const float*)d_in[6];
    const float* proj_w = (const float*)d_in[7];
    const float* proj_b = (const float*)d_in[8];
    const float* c1_lin = (const float*)d_in[9];
    const float* c1_as  = (const float*)d_in[10];
    const float* c1_ad  = (const float*)d_in[11];
    const float* c1_le  = (const float*)d_in[12];
    const float* c1_ae  = (const float*)d_in[13];
    const float* c1_b   = (const float*)d_in[14];
    const float* c2_lin = (const float*)d_in[15];
    const float* c2_as  = (const float*)d_in[16];
    const float* c2_ad  = (const float*)d_in[17];
    const float* c2_le  = (const float*)d_in[18];
    const float* c2_ae  = (const float*)d_in[19];
    const float* c2_b   = (const float*)d_in[20];
    const float* n1_g   = (const float*)d_in[21];
    const float* n1_b   = (const float*)d_in[22];
    const float* n2_g   = (const float*)d_in[23];
    const float* n2_b   = (const float*)d_in[24];
    const float* jk_w   = (const float*)d_in[25];
    const float* jk_b   = (const float*)d_in[26];
    const float* cls_w  = (const float*)d_in[27];
    const float* cls_b  = (const float*)d_in[28];
    float* out = (float*)d_out;

    k_init<<<291,256>>>(c1_le, c1_ae, c2_le, c2_ae, cls_w, cls_b, jk_w, jk_b);
    k_hist<<<(EE/4+255)/256,256>>>(ei);
    k_scan<<<1,1024>>>();
    k_edge<<<(EE+255)/256,256>>>(ea, ei, ee_w1, ee_b1, ee_w2, ee_b2);   // profiled slot
    k_node1<<<(NN+15)/16,128>>>(x, proj_w, proj_b, c1_lin, c1_as, c1_ad);
    k_gat<<<(NN+15)/16,512>>>(c1_b, n1_g, n1_b, 0);
    k_node2<<<(NN+127)/128,256>>>(c2_lin, c2_as, c2_ad);
    k_gat<<<(NN+15)/16,512>>>(c2_b, n2_g, n2_b, 1);
    k_out<<<(NN+7)/8,256>>>(out);
}